// round 5
// baseline (speedup 1.0000x reference)
#include <cuda_runtime.h>
#include <cuda_bf16.h>
#include <math.h>

// ---------------- problem constants ----------------
#define NLAYER   8
#define DMODEL   1024
#define NHEAD    16
#define HEADDIM  64
#define DFF      4096
#define VOCAB    4096
#define BATCH    4
#define SEQ      2048
#define MTOK     (BATCH*SEQ)      // 8192 tokens

// ---------------- scratch (device globals; no allocation allowed) ----------------
__device__ float g_x  [MTOK*DMODEL];     //  33.5 MB residual stream
__device__ float g_h  [MTOK*DMODEL];     //  33.5 MB ln output
__device__ float g_qkv[MTOK*3*DMODEL];   // 100.7 MB
__device__ float g_att[MTOK*DMODEL];     //  33.5 MB
__device__ float g_mid[MTOK*DFF];        // 134.2 MB
__device__ float g_tce[MTOK];
__device__ float g_tw [MTOK];
__device__ int   g_mflag;                // 1 = value_mask is uint8, 0 = int32

// ---------------- block reductions (deterministic) ----------------
__device__ __forceinline__ float blockReduceSum(float val) {
    __shared__ float sh[32];
    const int lane = threadIdx.x & 31, wid = threadIdx.x >> 5;
    #pragma unroll
    for (int o = 16; o; o >>= 1) val += __shfl_xor_sync(0xffffffffu, val, o);
    if (lane == 0) sh[wid] = val;
    __syncthreads();
    const int nw = (blockDim.x + 31) >> 5;
    float t = (threadIdx.x < nw) ? sh[threadIdx.x] : 0.0f;
    #pragma unroll
    for (int o = 16; o; o >>= 1) t += __shfl_xor_sync(0xffffffffu, t, o);
    if (threadIdx.x == 0) sh[0] = t;
    __syncthreads();
    t = sh[0];
    __syncthreads();
    return t;
}

__device__ __forceinline__ float blockReduceMax(float val) {
    __shared__ float sh[32];
    const int lane = threadIdx.x & 31, wid = threadIdx.x >> 5;
    #pragma unroll
    for (int o = 16; o; o >>= 1) val = fmaxf(val, __shfl_xor_sync(0xffffffffu, val, o));
    if (lane == 0) sh[wid] = val;
    __syncthreads();
    const int nw = (blockDim.x + 31) >> 5;
    float t = (threadIdx.x < nw) ? sh[threadIdx.x] : -INFINITY;
    #pragma unroll
    for (int o = 16; o; o >>= 1) t = fmaxf(t, __shfl_xor_sync(0xffffffffu, t, o));
    if (threadIdx.x == 0) sh[0] = t;
    __syncthreads();
    t = sh[0];
    __syncthreads();
    return t;
}

// ---------------- value_mask dtype probe ----------------
// If value_mask is int32 with values {0,1} (little-endian), every byte at
// offset i with (i & 3) != 0 inside the first 8192 bytes is 0.
// If it is uint8 {0,1}, ~3072 of those bytes are 1. Both layouts have at
// least 8192 valid bytes, so this never reads out of bounds.
__global__ __launch_bounds__(256) void detect_mask_kernel(const unsigned char* __restrict__ m)
{
    __shared__ int sh[32];
    int s = 0;
    for (int i = threadIdx.x; i < 8192; i += 256)
        if (i & 3) s += m[i];
    #pragma unroll
    for (int o = 16; o; o >>= 1) s += __shfl_xor_sync(0xffffffffu, s, o);
    const int lane = threadIdx.x & 31, wid = threadIdx.x >> 5;
    if (lane == 0) sh[wid] = s;
    __syncthreads();
    if (threadIdx.x < 8) {
        int t = sh[threadIdx.x];
        #pragma unroll
        for (int o = 4; o; o >>= 1) t += __shfl_xor_sync(0xffu, t, o);
        if (threadIdx.x == 0) g_mflag = (t != 0) ? 1 : 0;
    }
}

// ---------------- embed: x = tok_emb[ids] + pos_emb[t] ----------------
__global__ __launch_bounds__(256) void embed_kernel(
    const int* __restrict__ ids, const float* __restrict__ tok,
    const float* __restrict__ pos, float* __restrict__ x)
{
    const int m = blockIdx.x;
    const int t = m & (SEQ - 1);
    const int id = ids[m];
    const float4 a = ((const float4*)(tok + (size_t)id * DMODEL))[threadIdx.x];
    const float4 b = ((const float4*)(pos + (size_t)t  * DMODEL))[threadIdx.x];
    ((float4*)(x + (size_t)m * DMODEL))[threadIdx.x] =
        make_float4(a.x + b.x, a.y + b.y, a.z + b.z, a.w + b.w);
}

// ---------------- layernorm (row = 1024, block = 256 threads, 1 float4/thread) ----
__global__ __launch_bounds__(256) void ln_kernel(
    const float* __restrict__ x, const float* __restrict__ w,
    const float* __restrict__ b, float* __restrict__ y)
{
    const int row = blockIdx.x;
    const float4 v = ((const float4*)(x + (size_t)row * DMODEL))[threadIdx.x];
    float s = v.x + v.y + v.z + v.w;
    s = blockReduceSum(s);
    const float mu = s * (1.0f / DMODEL);
    const float d0 = v.x - mu, d1 = v.y - mu, d2 = v.z - mu, d3 = v.w - mu;
    float q = d0*d0 + d1*d1 + d2*d2 + d3*d3;
    q = blockReduceSum(q);
    const float rs = rsqrtf(q * (1.0f / DMODEL) + 1e-5f);
    const float4 w4 = ((const float4*)w)[threadIdx.x];
    const float4 b4 = ((const float4*)b)[threadIdx.x];
    float4 o;
    o.x = d0 * rs * w4.x + b4.x;
    o.y = d1 * rs * w4.y + b4.y;
    o.z = d2 * rs * w4.z + b4.z;
    o.w = d3 * rs * w4.w + b4.w;
    ((float4*)(y + (size_t)row * DMODEL))[threadIdx.x] = o;
}

// ---------------- SGEMM: C = A[MxK] * B + bias, epilogues ----------------
// TRANSB=false: B is [K,N] row-major.  TRANSB=true: B is [N,K] row-major (lm_head).
enum { EPI_NONE = 0, EPI_RES = 1, EPI_GELU = 2 };

template<bool TRANSB, int EPI>
__global__ __launch_bounds__(256, 2) void gemm_kernel(
    const float* __restrict__ A, const float* __restrict__ B,
    const float* __restrict__ bias, const float* __restrict__ res,
    float* __restrict__ C, int M, int N, int K)
{
    constexpr int BM = 128, BN = 128, BK = 16, TM = 8, TN = 8;
    __shared__ float As[BK][BM];
    __shared__ float Bs[BK][BN];
    const int tid = threadIdx.x;
    const int bm = blockIdx.y * BM;
    const int bn = blockIdx.x * BN;
    const int ty = tid >> 4, tx = tid & 15;

    float acc[TM][TN];
    #pragma unroll
    for (int i = 0; i < TM; i++)
        #pragma unroll
        for (int j = 0; j < TN; j++) acc[i][j] = 0.0f;

    const int a_row = tid >> 1;          // 0..127
    const int a_c4  = (tid & 1) * 2;     // float4 slot 0 or 2 (covers k cols 0..7 / 8..15)

    for (int k0 = 0; k0 < K; k0 += BK) {
        // ---- load A tile (128 x 16), store transposed ----
        {
            const float4* src = (const float4*)(A + (size_t)(bm + a_row) * K + k0) + a_c4;
            const float4 v0 = src[0], v1 = src[1];
            const int c = a_c4 * 4;
            As[c+0][a_row] = v0.x; As[c+1][a_row] = v0.y; As[c+2][a_row] = v0.z; As[c+3][a_row] = v0.w;
            As[c+4][a_row] = v1.x; As[c+5][a_row] = v1.y; As[c+6][a_row] = v1.z; As[c+7][a_row] = v1.w;
        }
        // ---- load B tile ----
        if (TRANSB) {
            const float4* src = (const float4*)(B + (size_t)(bn + a_row) * K + k0) + a_c4;
            const float4 v0 = src[0], v1 = src[1];
            const int c = a_c4 * 4;
            Bs[c+0][a_row] = v0.x; Bs[c+1][a_row] = v0.y; Bs[c+2][a_row] = v0.z; Bs[c+3][a_row] = v0.w;
            Bs[c+4][a_row] = v1.x; Bs[c+5][a_row] = v1.y; Bs[c+6][a_row] = v1.z; Bs[c+7][a_row] = v1.w;
        } else {
            const int br  = tid >> 4;            // 0..15
            const int bc4 = (2 * tid) & 31;      // float4 col
            const float4* src = (const float4*)(B + (size_t)(k0 + br) * N + bn) + bc4;
            const float4 v0 = src[0], v1 = src[1];
            *(float4*)&Bs[br][bc4 * 4]     = v0;
            *(float4*)&Bs[br][bc4 * 4 + 4] = v1;
        }
        __syncthreads();

        #pragma unroll
        for (int k = 0; k < BK; k++) {
            const float4 a0 = *(const float4*)&As[k][ty * TM];
            const float4 a1 = *(const float4*)&As[k][ty * TM + 4];
            const float4 b0 = *(const float4*)&Bs[k][tx * TN];
            const float4 b1 = *(const float4*)&Bs[k][tx * TN + 4];
            const float ar[8] = {a0.x, a0.y, a0.z, a0.w, a1.x, a1.y, a1.z, a1.w};
            const float br_[8] = {b0.x, b0.y, b0.z, b0.w, b1.x, b1.y, b1.z, b1.w};
            #pragma unroll
            for (int i = 0; i < TM; i++)
                #pragma unroll
                for (int j = 0; j < TN; j++) acc[i][j] += ar[i] * br_[j];
        }
        __syncthreads();
    }

    // ---- epilogue ----
    #pragma unroll
    for (int i = 0; i < TM; i++) {
        const int r = bm + ty * TM + i;
        float* crow = C + (size_t)r * N + bn + tx * TN;
        const float* rrow = (EPI == EPI_RES) ? (res + (size_t)r * N + bn + tx * TN) : nullptr;
        #pragma unroll
        for (int j = 0; j < TN; j++) {
            float v = acc[i][j];
            if (bias) v += bias[bn + tx * TN + j];
            if (EPI == EPI_GELU) v = 0.5f * v * (1.0f + erff(v * 0.70710678118654752f));
            if (EPI == EPI_RES)  v += rrow[j];
            crow[j] = v;
        }
    }
}

// ---------------- causal flash attention ----------------
// grid (T/64, H, B), block = 64 threads. Each thread owns one query row:
// q in regs (64), accumulator in regs (64), scores staged per-thread in smem column.
__global__ __launch_bounds__(64) void attn_kernel(
    const float* __restrict__ qkv, float* __restrict__ out)
{
    const int qt = blockIdx.x, h = blockIdx.y, b = blockIdx.z;
    const int tid = threadIdx.x;                 // 0..63 = query within tile
    const int qg = qt * 64 + tid;
    const size_t mrow = (size_t)b * SEQ + qg;

    __shared__ float Ks[32][64];
    __shared__ float Vs[32][64];
    __shared__ float Sp[32][64];                 // score scratch: Sp[j][tid]

    float qreg[64];
    {
        const float4* qp = (const float4*)(qkv + mrow * (3 * DMODEL) + h * HEADDIM);
        #pragma unroll
        for (int i = 0; i < 16; i++) {
            const float4 t = qp[i];
            qreg[4*i+0] = t.x; qreg[4*i+1] = t.y; qreg[4*i+2] = t.z; qreg[4*i+3] = t.w;
        }
    }

    float acc[64];
    #pragma unroll
    for (int d = 0; d < 64; d++) acc[d] = 0.0f;
    float m_i = -INFINITY, l_i = 0.0f;
    const float scale = 0.125f;                  // 1/sqrt(64)

    const float* kbase = qkv + (size_t)b * SEQ * (3 * DMODEL) + DMODEL     + h * HEADDIM;
    const float* vbase = qkv + (size_t)b * SEQ * (3 * DMODEL) + 2 * DMODEL + h * HEADDIM;

    const int nkt = 2 * qt + 2;                  // 32-row key tiles covering [0,(qt+1)*64)
    for (int kt = 0; kt < nkt; kt++) {
        // cooperative tile load (coalesced float4)
        {
            const int r0 = tid >> 4;             // 0..3
            const int c4 = tid & 15;             // float4 column
            #pragma unroll
            for (int it = 0; it < 8; it++) {
                const int r = it * 4 + r0;
                const size_t roff = (size_t)(kt * 32 + r) * (3 * DMODEL);
                *(float4*)&Ks[r][c4 * 4] = *(const float4*)(kbase + roff + c4 * 4);
                *(float4*)&Vs[r][c4 * 4] = *(const float4*)(vbase + roff + c4 * 4);
            }
        }
        __syncthreads();

        // pass 1: scores for my query row
        const int kg0 = kt * 32;
        float tmax = -INFINITY;
        #pragma unroll 2
        for (int j = 0; j < 32; j++) {
            float s = 0.0f;
            const float4* kr = (const float4*)Ks[j];
            #pragma unroll
            for (int i = 0; i < 16; i++) {
                const float4 kf = kr[i];
                s += qreg[4*i+0]*kf.x + qreg[4*i+1]*kf.y + qreg[4*i+2]*kf.z + qreg[4*i+3]*kf.w;
            }
            s *= scale;
            s = (kg0 + j <= qg) ? s : -INFINITY;
            Sp[j][tid] = s;
            tmax = fmaxf(tmax, s);
        }

        const float mnew = fmaxf(m_i, tmax);
        const float corr = expf(m_i - mnew);
        #pragma unroll
        for (int d = 0; d < 64; d++) acc[d] *= corr;

        // pass 2: exp + P*V
        float lsum = 0.0f;
        #pragma unroll 2
        for (int j = 0; j < 32; j++) {
            const float e = expf(Sp[j][tid] - mnew);
            lsum += e;
            const float4* vr = (const float4*)Vs[j];
            #pragma unroll
            for (int i = 0; i < 16; i++) {
                const float4 vf = vr[i];
                acc[4*i+0] += e * vf.x; acc[4*i+1] += e * vf.y;
                acc[4*i+2] += e * vf.z; acc[4*i+3] += e * vf.w;
            }
        }
        l_i = l_i * corr + lsum;
        m_i = mnew;
        __syncthreads();
    }

    const float inv = 1.0f / l_i;
    float4* op = (float4*)(out + mrow * DMODEL + h * HEADDIM);
    #pragma unroll
    for (int i = 0; i < 16; i++)
        op[i] = make_float4(acc[4*i+0]*inv, acc[4*i+1]*inv, acc[4*i+2]*inv, acc[4*i+3]*inv);
}

// ---------------- loss: per-token weighted CE (logits already in d_out) ----------
__global__ __launch_bounds__(256) void loss_token_kernel(
    const float* __restrict__ logits, const int* __restrict__ targets,
    const void* __restrict__ vmask,
    float* __restrict__ tce, float* __restrict__ tw)
{
    const int row = blockIdx.x;
    const float* lr = logits + (size_t)row * VOCAB;
    float v[16];
    #pragma unroll
    for (int i = 0; i < 16; i++) v[i] = lr[threadIdx.x + 256 * i];
    float mx = v[0];
    #pragma unroll
    for (int i = 1; i < 16; i++) mx = fmaxf(mx, v[i]);
    mx = blockReduceMax(mx);
    float se = 0.0f;
    #pragma unroll
    for (int i = 0; i < 16; i++) se += expf(v[i] - mx);
    se = blockReduceSum(se);
    if (threadIdx.x == 0) {
        const int tgt = targets[row];
        const float lse = mx + logf(se);
        const float nll = lse - lr[tgt];
        // dtype-robust mask read (flag set by detect_mask_kernel)
        int mv;
        if (g_mflag) mv = ((const unsigned char*)vmask)[row];
        else         mv = ((const int*)vmask)[row];
        const float w = 1.0f + 4.0f * ((mv != 0) ? 1.0f : 0.0f);   // VALUE_WEIGHT=5
        tce[row] = (tgt == 0 /*PAD*/) ? 0.0f : nll * w;
        tw[row]  = w;
    }
}

__global__ __launch_bounds__(256) void loss_final_kernel(
    const float* __restrict__ tce, const float* __restrict__ tw, float* __restrict__ out)
{
    float a = 0.0f, b = 0.0f;
    for (int i = threadIdx.x; i < MTOK; i += 256) { a += tce[i]; b += tw[i]; }
    a = blockReduceSum(a);
    b = blockReduceSum(b);
    if (threadIdx.x == 0) out[0] = a / b;
}

// ---------------- host driver ----------------
extern "C" void kernel_launch(void* const* d_in, const int* in_sizes, int n_in,
                              void* d_out, int out_size)
{
    (void)in_sizes; (void)n_in;
    const int*   ids   = (const int*)d_in[0];
    const int*   tgts  = (const int*)d_in[1];
    const void*  vmask = (const void*)d_in[2];
    const float* tok   = (const float*)d_in[3];
    const float* pos   = (const float*)d_in[4];
    const float* ln1w  = (const float*)d_in[5];
    const float* ln1b  = (const float*)d_in[6];
    const float* wqkv  = (const float*)d_in[7];
    const float* bqkv  = (const float*)d_in[8];
    const float* wproj = (const float*)d_in[9];
    const float* bproj = (const float*)d_in[10];
    const float* ln2w  = (const float*)d_in[11];
    const float* ln2b  = (const float*)d_in[12];
    const float* w1    = (const float*)d_in[13];
    const float* b1    = (const float*)d_in[14];
    const float* w2    = (const float*)d_in[15];
    const float* b2    = (const float*)d_in[16];
    const float* lnfw  = (const float*)d_in[17];
    const float* lnfb  = (const float*)d_in[18];
    float* out = (float*)d_out;

    float *x, *h, *qkv, *att, *mid, *tce, *tw;
    cudaGetSymbolAddress((void**)&x,   g_x);
    cudaGetSymbolAddress((void**)&h,   g_h);
    cudaGetSymbolAddress((void**)&qkv, g_qkv);
    cudaGetSymbolAddress((void**)&att, g_att);
    cudaGetSymbolAddress((void**)&mid, g_mid);
    cudaGetSymbolAddress((void**)&tce, g_tce);
    cudaGetSymbolAddress((void**)&tw,  g_tw);

    detect_mask_kernel<<<1, 256>>>((const unsigned char*)vmask);

    embed_kernel<<<MTOK, 256>>>(ids, tok, pos, x);

    for (int l = 0; l < NLAYER; l++) {
        ln_kernel<<<MTOK, 256>>>(x, ln1w + l * DMODEL, ln1b + l * DMODEL, h);

        gemm_kernel<false, EPI_NONE><<<dim3(3 * DMODEL / 128, MTOK / 128), 256>>>(
            h, wqkv + (size_t)l * DMODEL * 3 * DMODEL, bqkv + (size_t)l * 3 * DMODEL,
            nullptr, qkv, MTOK, 3 * DMODEL, DMODEL);

        attn_kernel<<<dim3(SEQ / 64, NHEAD, BATCH), 64>>>(qkv, att);

        gemm_kernel<false, EPI_RES><<<dim3(DMODEL / 128, MTOK / 128), 256>>>(
            att, wproj + (size_t)l * DMODEL * DMODEL, bproj + (size_t)l * DMODEL,
            x, x, MTOK, DMODEL, DMODEL);

        ln_kernel<<<MTOK, 256>>>(x, ln2w + l * DMODEL, ln2b + l * DMODEL, h);

        gemm_kernel<false, EPI_GELU><<<dim3(DFF / 128, MTOK / 128), 256>>>(
            h, w1 + (size_t)l * DMODEL * DFF, b1 + (size_t)l * DFF,
            nullptr, mid, MTOK, DFF, DMODEL);

        gemm_kernel<false, EPI_RES><<<dim3(DMODEL / 128, MTOK / 128), 256>>>(
            mid, w2 + (size_t)l * DFF * DMODEL, b2 + (size_t)l * DMODEL,
            x, x, MTOK, DMODEL, DFF);
    }

    ln_kernel<<<MTOK, 256>>>(x, lnfw, lnfb, h);

    // logits = h @ token_emb^T  (NT gemm, no bias) -> d_out
    gemm_kernel<true, EPI_NONE><<<dim3(VOCAB / 128, MTOK / 128), 256>>>(
        h, tok, nullptr, nullptr, out, MTOK, VOCAB, DMODEL);

    if (out_size > MTOK * VOCAB) {
        loss_token_kernel<<<MTOK, 256>>>(out, tgts, vmask, tce, tw);
        loss_final_kernel<<<1, 256>>>(tce, tw, out + (size_t)MTOK * VOCAB);
    }
}

// round 6
// speedup vs baseline: 1.7409x; 1.7409x over previous
#include <cuda_runtime.h>
#include <cuda_bf16.h>
#include <math.h>
#include <stdint.h>

// ---------------- problem constants ----------------
#define NLAYER   8
#define DMODEL   1024
#define NHEAD    16
#define HEADDIM  64
#define DFF      4096
#define VOCAB    4096
#define BATCH    4
#define SEQ      2048
#define MTOK     (BATCH*SEQ)      // 8192 tokens

// ---------------- scratch (device globals; no allocation allowed) ----------------
__device__ float g_x  [MTOK*DMODEL];       // residual stream (fp32)
__device__ float g_qkv[MTOK*3*DMODEL];     // qkv (fp32, attention input)
__device__ __nv_bfloat16 g_hhi[MTOK*DMODEL];   // activation hi (ln out / attn out)
__device__ __nv_bfloat16 g_hlo[MTOK*DMODEL];   // activation lo
__device__ __nv_bfloat16 g_mhi[MTOK*DFF];      // gelu out hi
__device__ __nv_bfloat16 g_mlo[MTOK*DFF];      // gelu out lo
// packed split weights: u32 word (kp, n) = (bf16(W[2kp+1][n])<<16) | bf16(W[2kp][n])
__device__ uint32_t g_wqkv_hi[NLAYER*(DMODEL/2)*3*DMODEL];
__device__ uint32_t g_wqkv_lo[NLAYER*(DMODEL/2)*3*DMODEL];
__device__ uint32_t g_wproj_hi[NLAYER*(DMODEL/2)*DMODEL];
__device__ uint32_t g_wproj_lo[NLAYER*(DMODEL/2)*DMODEL];
__device__ uint32_t g_w1_hi[NLAYER*(DMODEL/2)*DFF];
__device__ uint32_t g_w1_lo[NLAYER*(DMODEL/2)*DFF];
__device__ uint32_t g_w2_hi[NLAYER*(DFF/2)*DMODEL];
__device__ uint32_t g_w2_lo[NLAYER*(DFF/2)*DMODEL];
__device__ uint32_t g_lmh_hi[(DMODEL/2)*VOCAB];
__device__ uint32_t g_lmh_lo[(DMODEL/2)*VOCAB];
__device__ float g_tce[MTOK];
__device__ float g_tw [MTOK];
__device__ int   g_mflag;                  // 1 = value_mask is uint8, 0 = int32

// ---------------- block reductions (deterministic) ----------------
__device__ __forceinline__ float blockReduceSum(float val) {
    __shared__ float sh[32];
    const int lane = threadIdx.x & 31, wid = threadIdx.x >> 5;
    #pragma unroll
    for (int o = 16; o; o >>= 1) val += __shfl_xor_sync(0xffffffffu, val, o);
    if (lane == 0) sh[wid] = val;
    __syncthreads();
    const int nw = (blockDim.x + 31) >> 5;
    float t = (threadIdx.x < nw) ? sh[threadIdx.x] : 0.0f;
    #pragma unroll
    for (int o = 16; o; o >>= 1) t += __shfl_xor_sync(0xffffffffu, t, o);
    if (threadIdx.x == 0) sh[0] = t;
    __syncthreads();
    t = sh[0];
    __syncthreads();
    return t;
}

__device__ __forceinline__ float blockReduceMax(float val) {
    __shared__ float sh[32];
    const int lane = threadIdx.x & 31, wid = threadIdx.x >> 5;
    #pragma unroll
    for (int o = 16; o; o >>= 1) val = fmaxf(val, __shfl_xor_sync(0xffffffffu, val, o));
    if (lane == 0) sh[wid] = val;
    __syncthreads();
    const int nw = (blockDim.x + 31) >> 5;
    float t = (threadIdx.x < nw) ? sh[threadIdx.x] : -INFINITY;
    #pragma unroll
    for (int o = 16; o; o >>= 1) t = fmaxf(t, __shfl_xor_sync(0xffffffffu, t, o));
    if (threadIdx.x == 0) sh[0] = t;
    __syncthreads();
    t = sh[0];
    __syncthreads();
    return t;
}

// ---------------- hi/lo bf16 split helper ----------------
__device__ __forceinline__ void split_bf16(float a, __nv_bfloat16& hi, __nv_bfloat16& lo) {
    hi = __float2bfloat16(a);
    lo = __float2bfloat16(a - __bfloat162float(hi));
}

// ---------------- weight split/pack kernels ----------------
// W [K][N] fp32 -> hi/lo u32 [K/2][N]; grid (N/256, K/2, L), W layer stride K*N
__global__ __launch_bounds__(256) void convw_kernel(
    const float* __restrict__ W, uint32_t* __restrict__ Whi, uint32_t* __restrict__ Wlo,
    int K, int N)
{
    const int n  = blockIdx.x * 256 + threadIdx.x;
    const int kp = blockIdx.y;
    const int l  = blockIdx.z;
    const float* Wl = W + (size_t)l * K * N;
    const float a0 = Wl[(size_t)(2 * kp)     * N + n];
    const float a1 = Wl[(size_t)(2 * kp + 1) * N + n];
    __nv_bfloat16 h0, l0, h1, l1;
    split_bf16(a0, h0, l0);
    split_bf16(a1, h1, l1);
    const size_t o = (size_t)l * (K / 2) * N + (size_t)kp * N + n;
    Whi[o] = ((uint32_t)__bfloat16_as_ushort(h1) << 16) | __bfloat16_as_ushort(h0);
    Wlo[o] = ((uint32_t)__bfloat16_as_ushort(l1) << 16) | __bfloat16_as_ushort(l0);
}

// W [N][K] fp32 (lm_head = token_emb) -> hi/lo u32 [K/2][N]; grid (K/512, N)
__global__ __launch_bounds__(256) void convw_t_kernel(
    const float* __restrict__ W, uint32_t* __restrict__ Whi, uint32_t* __restrict__ Wlo,
    int K, int N)
{
    const int kp = blockIdx.x * 256 + threadIdx.x;
    const int n  = blockIdx.y;
    const float2 a = *(const float2*)(W + (size_t)n * K + 2 * kp);
    __nv_bfloat16 h0, l0, h1, l1;
    split_bf16(a.x, h0, l0);
    split_bf16(a.y, h1, l1);
    const size_t o = (size_t)kp * N + n;
    Whi[o] = ((uint32_t)__bfloat16_as_ushort(h1) << 16) | __bfloat16_as_ushort(h0);
    Wlo[o] = ((uint32_t)__bfloat16_as_ushort(l1) << 16) | __bfloat16_as_ushort(l0);
}

// ---------------- value_mask dtype probe ----------------
__global__ __launch_bounds__(256) void detect_mask_kernel(const unsigned char* __restrict__ m)
{
    __shared__ int sh[32];
    int s = 0;
    for (int i = threadIdx.x; i < 8192; i += 256)
        if (i & 3) s += m[i];
    #pragma unroll
    for (int o = 16; o; o >>= 1) s += __shfl_xor_sync(0xffffffffu, s, o);
    const int lane = threadIdx.x & 31, wid = threadIdx.x >> 5;
    if (lane == 0) sh[wid] = s;
    __syncthreads();
    if (threadIdx.x < 8) {
        int t = sh[threadIdx.x];
        #pragma unroll
        for (int o = 4; o; o >>= 1) t += __shfl_xor_sync(0xffu, t, o);
        if (threadIdx.x == 0) g_mflag = (t != 0) ? 1 : 0;
    }
}

// ---------------- embed ----------------
__global__ __launch_bounds__(256) void embed_kernel(
    const int* __restrict__ ids, const float* __restrict__ tok,
    const float* __restrict__ pos, float* __restrict__ x)
{
    const int m = blockIdx.x;
    const int t = m & (SEQ - 1);
    const int id = ids[m];
    const float4 a = ((const float4*)(tok + (size_t)id * DMODEL))[threadIdx.x];
    const float4 b = ((const float4*)(pos + (size_t)t  * DMODEL))[threadIdx.x];
    ((float4*)(x + (size_t)m * DMODEL))[threadIdx.x] =
        make_float4(a.x + b.x, a.y + b.y, a.z + b.z, a.w + b.w);
}

// ---------------- layernorm -> split bf16 outputs ----------------
__global__ __launch_bounds__(256) void ln_bf16_kernel(
    const float* __restrict__ x, const float* __restrict__ w,
    const float* __restrict__ b, __nv_bfloat16* __restrict__ yhi,
    __nv_bfloat16* __restrict__ ylo)
{
    const int row = blockIdx.x;
    const float4 v = ((const float4*)(x + (size_t)row * DMODEL))[threadIdx.x];
    float s = v.x + v.y + v.z + v.w;
    s = blockReduceSum(s);
    const float mu = s * (1.0f / DMODEL);
    const float d0 = v.x - mu, d1 = v.y - mu, d2 = v.z - mu, d3 = v.w - mu;
    float q = d0*d0 + d1*d1 + d2*d2 + d3*d3;
    q = blockReduceSum(q);
    const float rs = rsqrtf(q * (1.0f / DMODEL) + 1e-5f);
    const float4 w4 = ((const float4*)w)[threadIdx.x];
    const float4 b4 = ((const float4*)b)[threadIdx.x];
    float o0 = d0 * rs * w4.x + b4.x;
    float o1 = d1 * rs * w4.y + b4.y;
    float o2 = d2 * rs * w4.z + b4.z;
    float o3 = d3 * rs * w4.w + b4.w;
    __nv_bfloat16 h0,l0,h1,l1,h2,l2,h3,l3;
    split_bf16(o0,h0,l0); split_bf16(o1,h1,l1); split_bf16(o2,h2,l2); split_bf16(o3,h3,l3);
    const size_t base = (size_t)row * DMODEL + threadIdx.x * 4;
    *(__nv_bfloat162*)(yhi + base)     = __halves2bfloat162(h0, h1);
    *(__nv_bfloat162*)(yhi + base + 2) = __halves2bfloat162(h2, h3);
    *(__nv_bfloat162*)(ylo + base)     = __halves2bfloat162(l0, l1);
    *(__nv_bfloat162*)(ylo + base + 2) = __halves2bfloat162(l2, l3);
}

// ---------------- split-bf16 tensor-core GEMM ----------------
// C[M,N] = (Ahi+Alo)[M,K] * (Bhi+Blo)[K,N] via 3 bf16 mma products, fp32 accum.
// A: row-major bf16 arrays. B: pre-packed u32 [K/2][N] (k-pair interleaved).
enum { EPI_NONE = 0, EPI_RES = 1, EPI_GELU = 2 };

__device__ __forceinline__ void mma16816(float* d, const uint32_t* a, const uint32_t* b) {
    asm volatile(
        "mma.sync.aligned.m16n8k16.row.col.f32.bf16.bf16.f32 "
        "{%0,%1,%2,%3}, {%4,%5,%6,%7}, {%8,%9}, {%0,%1,%2,%3};"
        : "+f"(d[0]), "+f"(d[1]), "+f"(d[2]), "+f"(d[3])
        : "r"(a[0]), "r"(a[1]), "r"(a[2]), "r"(a[3]), "r"(b[0]), "r"(b[1]));
}

template<int EPI>
__global__ __launch_bounds__(256, 2) void gemm_bf16s_kernel(
    const __nv_bfloat16* __restrict__ Ahi_, const __nv_bfloat16* __restrict__ Alo_,
    const uint32_t* __restrict__ Bhi, const uint32_t* __restrict__ Blo,
    const float* __restrict__ bias, const float* __restrict__ res,
    float* __restrict__ C, __nv_bfloat16* __restrict__ Chi, __nv_bfloat16* __restrict__ Clo,
    int M, int N, int K)
{
    constexpr int BM = 128, BN = 128, BK = 32;          // k elements per tile
    constexpr int SA = 20, SB = 136;                    // smem strides (u32), conflict-free
    __shared__ uint32_t sAh[BM][SA], sAl[BM][SA];       // [row][kpair]
    __shared__ uint32_t sBh[BK/2][SB], sBl[BK/2][SB];   // [kpair][col]

    const int tid = threadIdx.x;
    const int bm = blockIdx.y * BM;
    const int bn = blockIdx.x * BN;
    const int K2 = K >> 1;
    const uint32_t* A32h = (const uint32_t*)Ahi_;
    const uint32_t* A32l = (const uint32_t*)Alo_;

    const int lane = tid & 31;
    const int g = lane >> 2;          // groupID 0..7
    const int t = lane & 3;           // threadID-in-group
    const int w = tid >> 5;
    const int wm = w >> 2, wn = w & 3;  // warp tile (wm*64, wn*32)

    float acc[4][4][4];
    #pragma unroll
    for (int mt = 0; mt < 4; mt++)
        #pragma unroll
        for (int nt = 0; nt < 4; nt++)
            #pragma unroll
            for (int i = 0; i < 4; i++) acc[mt][nt][i] = 0.0f;

    for (int kt = 0; kt < K; kt += BK) {
        const int kp0 = kt >> 1;
        // ---- A tiles: 128 rows x 16 u32 each (hi, lo) ----
        #pragma unroll
        for (int i = 0; i < 2; i++) {
            const int f = tid + 256 * i;          // 0..511
            const int r = f >> 2, c4 = (f & 3) << 2;
            const size_t go = (size_t)(bm + r) * K2 + kp0 + c4;
            uint4 vh = *(const uint4*)(A32h + go);
            uint4 vl = *(const uint4*)(A32l + go);
            sAh[r][c4+0]=vh.x; sAh[r][c4+1]=vh.y; sAh[r][c4+2]=vh.z; sAh[r][c4+3]=vh.w;
            sAl[r][c4+0]=vl.x; sAl[r][c4+1]=vl.y; sAl[r][c4+2]=vl.z; sAl[r][c4+3]=vl.w;
        }
        // ---- B tiles: 16 kpairs x 128 u32 each ----
        #pragma unroll
        for (int i = 0; i < 2; i++) {
            const int f = tid + 256 * i;
            const int kp = f >> 5, c4 = (f & 31) << 2;
            const size_t go = (size_t)(kp0 + kp) * N + bn + c4;
            uint4 vh = *(const uint4*)(Bhi + go);
            uint4 vl = *(const uint4*)(Blo + go);
            sBh[kp][c4+0]=vh.x; sBh[kp][c4+1]=vh.y; sBh[kp][c4+2]=vh.z; sBh[kp][c4+3]=vh.w;
            sBl[kp][c4+0]=vl.x; sBl[kp][c4+1]=vl.y; sBl[kp][c4+2]=vl.z; sBl[kp][c4+3]=vl.w;
        }
        __syncthreads();

        #pragma unroll
        for (int ks = 0; ks < 2; ks++) {            // two k16 steps per tile
            const int kb = ks * 8;
            uint32_t bh[4][2], bl[4][2];
            #pragma unroll
            for (int nt = 0; nt < 4; nt++) {
                const int col = wn * 32 + nt * 8 + g;
                bh[nt][0] = sBh[kb + t][col];
                bh[nt][1] = sBh[kb + t + 4][col];
                bl[nt][0] = sBl[kb + t][col];
                bl[nt][1] = sBl[kb + t + 4][col];
            }
            #pragma unroll
            for (int mt = 0; mt < 4; mt++) {
                const int row = wm * 64 + mt * 16 + g;
                uint32_t ah[4], al[4];
                ah[0] = sAh[row    ][kb + t];
                ah[1] = sAh[row + 8][kb + t];
                ah[2] = sAh[row    ][kb + t + 4];
                ah[3] = sAh[row + 8][kb + t + 4];
                al[0] = sAl[row    ][kb + t];
                al[1] = sAl[row + 8][kb + t];
                al[2] = sAl[row    ][kb + t + 4];
                al[3] = sAl[row + 8][kb + t + 4];
                #pragma unroll
                for (int nt = 0; nt < 4; nt++) mma16816(acc[mt][nt], ah, bh[nt]);
                #pragma unroll
                for (int nt = 0; nt < 4; nt++) mma16816(acc[mt][nt], ah, bl[nt]);
                #pragma unroll
                for (int nt = 0; nt < 4; nt++) mma16816(acc[mt][nt], al, bh[nt]);
            }
        }
        __syncthreads();
    }

    // ---- epilogue ----
    #pragma unroll
    for (int mt = 0; mt < 4; mt++) {
        #pragma unroll
        for (int nt = 0; nt < 4; nt++) {
            const int col = bn + wn * 32 + nt * 8 + 2 * t;
            #pragma unroll
            for (int half = 0; half < 2; half++) {
                const int row = bm + wm * 64 + mt * 16 + g + half * 8;
                float v0 = acc[mt][nt][2 * half + 0];
                float v1 = acc[mt][nt][2 * half + 1];
                if (bias) { v0 += bias[col]; v1 += bias[col + 1]; }
                const size_t o = (size_t)row * N + col;
                if (EPI == EPI_GELU) {
                    v0 = 0.5f * v0 * (1.0f + erff(v0 * 0.70710678118654752f));
                    v1 = 0.5f * v1 * (1.0f + erff(v1 * 0.70710678118654752f));
                    __nv_bfloat16 h0, l0, h1, l1;
                    split_bf16(v0, h0, l0);
                    split_bf16(v1, h1, l1);
                    *(__nv_bfloat162*)(Chi + o) = __halves2bfloat162(h0, h1);
                    *(__nv_bfloat162*)(Clo + o) = __halves2bfloat162(l0, l1);
                } else {
                    if (EPI == EPI_RES) {
                        const float2 r2 = *(const float2*)(res + o);
                        v0 += r2.x; v1 += r2.y;
                    }
                    *(float2*)(C + o) = make_float2(v0, v1);
                }
            }
        }
    }
}

// ---------------- causal flash attention (fp32, split-bf16 output) ----------------
__global__ __launch_bounds__(64) void attn_kernel(
    const float* __restrict__ qkv,
    __nv_bfloat16* __restrict__ ohi, __nv_bfloat16* __restrict__ olo)
{
    const int qt = blockIdx.x, h = blockIdx.y, b = blockIdx.z;
    const int tid = threadIdx.x;
    const int qg = qt * 64 + tid;
    const size_t mrow = (size_t)b * SEQ + qg;

    __shared__ float Ks[32][64];
    __shared__ float Vs[32][64];
    __shared__ float Sp[32][64];

    float qreg[64];
    {
        const float4* qp = (const float4*)(qkv + mrow * (3 * DMODEL) + h * HEADDIM);
        #pragma unroll
        for (int i = 0; i < 16; i++) {
            const float4 t4 = qp[i];
            qreg[4*i+0] = t4.x; qreg[4*i+1] = t4.y; qreg[4*i+2] = t4.z; qreg[4*i+3] = t4.w;
        }
    }

    float acc[64];
    #pragma unroll
    for (int d = 0; d < 64; d++) acc[d] = 0.0f;
    float m_i = -INFINITY, l_i = 0.0f;
    const float scale = 0.125f;

    const float* kbase = qkv + (size_t)b * SEQ * (3 * DMODEL) + DMODEL     + h * HEADDIM;
    const float* vbase = qkv + (size_t)b * SEQ * (3 * DMODEL) + 2 * DMODEL + h * HEADDIM;

    const int nkt = 2 * qt + 2;
    for (int kt = 0; kt < nkt; kt++) {
        {
            const int r0 = tid >> 4;
            const int c4 = tid & 15;
            #pragma unroll
            for (int it = 0; it < 8; it++) {
                const int r = it * 4 + r0;
                const size_t roff = (size_t)(kt * 32 + r) * (3 * DMODEL);
                *(float4*)&Ks[r][c4 * 4] = *(const float4*)(kbase + roff + c4 * 4);
                *(float4*)&Vs[r][c4 * 4] = *(const float4*)(vbase + roff + c4 * 4);
            }
        }
        __syncthreads();

        const int kg0 = kt * 32;
        float tmax = -INFINITY;
        #pragma unroll 2
        for (int j = 0; j < 32; j++) {
            float s = 0.0f;
            const float4* kr = (const float4*)Ks[j];
            #pragma unroll
            for (int i = 0; i < 16; i++) {
                const float4 kf = kr[i];
                s += qreg[4*i+0]*kf.x + qreg[4*i+1]*kf.y + qreg[4*i+2]*kf.z + qreg[4*i+3]*kf.w;
            }
            s *= scale;
            s = (kg0 + j <= qg) ? s : -INFINITY;
            Sp[j][tid] = s;
            tmax = fmaxf(tmax, s);
        }

        const float mnew = fmaxf(m_i, tmax);
        const float corr = expf(m_i - mnew);
        #pragma unroll
        for (int d = 0; d < 64; d++) acc[d] *= corr;

        float lsum = 0.0f;
        #pragma unroll 2
        for (int j = 0; j < 32; j++) {
            const float e = expf(Sp[j][tid] - mnew);
            lsum += e;
            const float4* vr = (const float4*)Vs[j];
            #pragma unroll
            for (int i = 0; i < 16; i++) {
                const float4 vf = vr[i];
                acc[4*i+0] += e * vf.x; acc[4*i+1] += e * vf.y;
                acc[4*i+2] += e * vf.z; acc[4*i+3] += e * vf.w;
            }
        }
        l_i = l_i * corr + lsum;
        m_i = mnew;
        __syncthreads();
    }

    const float inv = 1.0f / l_i;
    const size_t obase = mrow * DMODEL + h * HEADDIM;
    #pragma unroll
    for (int i = 0; i < 16; i++) {
        const float v0 = acc[4*i+0]*inv, v1 = acc[4*i+1]*inv;
        const float v2 = acc[4*i+2]*inv, v3 = acc[4*i+3]*inv;
        __nv_bfloat16 h0,l0,h1,l1,h2,l2,h3,l3;
        split_bf16(v0,h0,l0); split_bf16(v1,h1,l1); split_bf16(v2,h2,l2); split_bf16(v3,h3,l3);
        *(__nv_bfloat162*)(ohi + obase + 4*i)     = __halves2bfloat162(h0, h1);
        *(__nv_bfloat162*)(ohi + obase + 4*i + 2) = __halves2bfloat162(h2, h3);
        *(__nv_bfloat162*)(olo + obase + 4*i)     = __halves2bfloat162(l0, l1);
        *(__nv_bfloat162*)(olo + obase + 4*i + 2) = __halves2bfloat162(l2, l3);
    }
}

// ---------------- loss ----------------
__global__ __launch_bounds__(256) void loss_token_kernel(
    const float* __restrict__ logits, const int* __restrict__ targets,
    const void* __restrict__ vmask,
    float* __restrict__ tce, float* __restrict__ tw)
{
    const int row = blockIdx.x;
    const float* lr = logits + (size_t)row * VOCAB;
    float v[16];
    #pragma unroll
    for (int i = 0; i < 16; i++) v[i] = lr[threadIdx.x + 256 * i];
    float mx = v[0];
    #pragma unroll
    for (int i = 1; i < 16; i++) mx = fmaxf(mx, v[i]);
    mx = blockReduceMax(mx);
    float se = 0.0f;
    #pragma unroll
    for (int i = 0; i < 16; i++) se += expf(v[i] - mx);
    se = blockReduceSum(se);
    if (threadIdx.x == 0) {
        const int tgt = targets[row];
        const float lse = mx + logf(se);
        const float nll = lse - lr[tgt];
        int mv;
        if (g_mflag) mv = ((const unsigned char*)vmask)[row];
        else         mv = ((const int*)vmask)[row];
        const float w = 1.0f + 4.0f * ((mv != 0) ? 1.0f : 0.0f);
        tce[row] = (tgt == 0) ? 0.0f : nll * w;
        tw[row]  = w;
    }
}

__global__ __launch_bounds__(256) void loss_final_kernel(
    const float* __restrict__ tce, const float* __restrict__ tw, float* __restrict__ out)
{
    float a = 0.0f, b = 0.0f;
    for (int i = threadIdx.x; i < MTOK; i += 256) { a += tce[i]; b += tw[i]; }
    a = blockReduceSum(a);
    b = blockReduceSum(b);
    if (threadIdx.x == 0) out[0] = a / b;
}

// ---------------- host driver ----------------
extern "C" void kernel_launch(void* const* d_in, const int* in_sizes, int n_in,
                              void* d_out, int out_size)
{
    (void)in_sizes; (void)n_in;
    const int*   ids   = (const int*)d_in[0];
    const int*   tgts  = (const int*)d_in[1];
    const void*  vmask = (const void*)d_in[2];
    const float* tok   = (const float*)d_in[3];
    const float* pos   = (const float*)d_in[4];
    const float* ln1w  = (const float*)d_in[5];
    const float* ln1b  = (const float*)d_in[6];
    const float* wqkv  = (const float*)d_in[7];
    const float* bqkv  = (const float*)d_in[8];
    const float* wproj = (const float*)d_in[9];
    const float* bproj = (const float*)d_in[10];
    const float* ln2w  = (const float*)d_in[11];
    const float* ln2b  = (const float*)d_in[12];
    const float* w1    = (const float*)d_in[13];
    const float* b1    = (const float*)d_in[14];
    const float* w2    = (const float*)d_in[15];
    const float* b2    = (const float*)d_in[16];
    const float* lnfw  = (const float*)d_in[17];
    const float* lnfb  = (const float*)d_in[18];
    float* out = (float*)d_out;

    float *x, *qkv, *tce, *tw;
    __nv_bfloat16 *hhi, *hlo, *mhi, *mlo;
    uint32_t *wq_hi, *wq_lo, *wp_hi, *wp_lo, *w1_hi, *w1_lo, *w2_hi, *w2_lo, *lm_hi, *lm_lo;
    cudaGetSymbolAddress((void**)&x,    g_x);
    cudaGetSymbolAddress((void**)&qkv,  g_qkv);
    cudaGetSymbolAddress((void**)&hhi,  g_hhi);
    cudaGetSymbolAddress((void**)&hlo,  g_hlo);
    cudaGetSymbolAddress((void**)&mhi,  g_mhi);
    cudaGetSymbolAddress((void**)&mlo,  g_mlo);
    cudaGetSymbolAddress((void**)&wq_hi, g_wqkv_hi);
    cudaGetSymbolAddress((void**)&wq_lo, g_wqkv_lo);
    cudaGetSymbolAddress((void**)&wp_hi, g_wproj_hi);
    cudaGetSymbolAddress((void**)&wp_lo, g_wproj_lo);
    cudaGetSymbolAddress((void**)&w1_hi, g_w1_hi);
    cudaGetSymbolAddress((void**)&w1_lo, g_w1_lo);
    cudaGetSymbolAddress((void**)&w2_hi, g_w2_hi);
    cudaGetSymbolAddress((void**)&w2_lo, g_w2_lo);
    cudaGetSymbolAddress((void**)&lm_hi, g_lmh_hi);
    cudaGetSymbolAddress((void**)&lm_lo, g_lmh_lo);
    cudaGetSymbolAddress((void**)&tce,  g_tce);
    cudaGetSymbolAddress((void**)&tw,   g_tw);

    // ---- split/pack weights (per replay; ~170us of HBM traffic) ----
    convw_kernel<<<dim3(3*DMODEL/256, DMODEL/2, NLAYER), 256>>>(wqkv,  wq_hi, wq_lo, DMODEL, 3*DMODEL);
    convw_kernel<<<dim3(DMODEL/256,   DMODEL/2, NLAYER), 256>>>(wproj, wp_hi, wp_lo, DMODEL, DMODEL);
    convw_kernel<<<dim3(DFF/256,      DMODEL/2, NLAYER), 256>>>(w1,    w1_hi, w1_lo, DMODEL, DFF);
    convw_kernel<<<dim3(DMODEL/256,   DFF/2,    NLAYER), 256>>>(w2,    w2_hi, w2_lo, DFF,    DMODEL);
    convw_t_kernel<<<dim3((DMODEL/2)/256, VOCAB), 256>>>(tok, lm_hi, lm_lo, DMODEL, VOCAB);

    detect_mask_kernel<<<1, 256>>>((const unsigned char*)vmask);
    embed_kernel<<<MTOK, 256>>>(ids, tok, pos, x);

    const size_t wq_stride = (size_t)(DMODEL/2) * 3 * DMODEL;
    const size_t wp_stride = (size_t)(DMODEL/2) * DMODEL;
    const size_t w1_stride = (size_t)(DMODEL/2) * DFF;
    const size_t w2_stride = (size_t)(DFF/2)    * DMODEL;

    for (int l = 0; l < NLAYER; l++) {
        ln_bf16_kernel<<<MTOK, 256>>>(x, ln1w + l*DMODEL, ln1b + l*DMODEL, hhi, hlo);

        gemm_bf16s_kernel<EPI_NONE><<<dim3(3*DMODEL/128, MTOK/128), 256>>>(
            hhi, hlo, wq_hi + l*wq_stride, wq_lo + l*wq_stride,
            bqkv + (size_t)l*3*DMODEL, nullptr, qkv, nullptr, nullptr,
            MTOK, 3*DMODEL, DMODEL);

        attn_kernel<<<dim3(SEQ/64, NHEAD, BATCH), 64>>>(qkv, hhi, hlo);

        gemm_bf16s_kernel<EPI_RES><<<dim3(DMODEL/128, MTOK/128), 256>>>(
            hhi, hlo, wp_hi + l*wp_stride, wp_lo + l*wp_stride,
            bproj + (size_t)l*DMODEL, x, x, nullptr, nullptr,
            MTOK, DMODEL, DMODEL);

        ln_bf16_kernel<<<MTOK, 256>>>(x, ln2w + l*DMODEL, ln2b + l*DMODEL, hhi, hlo);

        gemm_bf16s_kernel<EPI_GELU><<<dim3(DFF/128, MTOK/128), 256>>>(
            hhi, hlo, w1_hi + l*w1_stride, w1_lo + l*w1_stride,
            b1 + (size_t)l*DFF, nullptr, nullptr, mhi, mlo,
            MTOK, DFF, DMODEL);

        gemm_bf16s_kernel<EPI_RES><<<dim3(DMODEL/128, MTOK/128), 256>>>(
            mhi, mlo, w2_hi + l*w2_stride, w2_lo + l*w2_stride,
            b2 + (size_t)l*DMODEL, x, x, nullptr, nullptr,
            MTOK, DMODEL, DFF);
    }

    ln_bf16_kernel<<<MTOK, 256>>>(x, lnfw, lnfb, hhi, hlo);

    gemm_bf16s_kernel<EPI_NONE><<<dim3(VOCAB/128, MTOK/128), 256>>>(
        hhi, hlo, lm_hi, lm_lo, nullptr, nullptr, out, nullptr, nullptr,
        MTOK, VOCAB, DMODEL);

    if (out_size > MTOK * VOCAB) {
        loss_token_kernel<<<MTOK, 256>>>(out, tgts, vmask, tce, tw);
        loss_final_kernel<<<1, 256>>>(tce, tw, out + (size_t)MTOK * VOCAB);
    }
}

// round 7
// speedup vs baseline: 1.8775x; 1.0785x over previous
#include <cuda_runtime.h>
#include <cuda_bf16.h>
#include <math.h>
#include <stdint.h>

// ---------------- problem constants ----------------
#define NLAYER   8
#define DMODEL   1024
#define NHEAD    16
#define HEADDIM  64
#define DFF      4096
#define VOCAB    4096
#define BATCH    4
#define SEQ      2048
#define MTOK     (BATCH*SEQ)      // 8192 tokens

// ---------------- scratch (device globals; no allocation allowed) ----------------
__device__ float g_x  [MTOK*DMODEL];       // residual stream (fp32)
__device__ float g_qkv[MTOK*3*DMODEL];     // qkv (fp32, attention input)
__device__ __nv_bfloat16 g_hhi[MTOK*DMODEL];   // activation hi (ln out / attn out)
__device__ __nv_bfloat16 g_hlo[MTOK*DMODEL];   // activation lo
__device__ __nv_bfloat16 g_mhi[MTOK*DFF];      // gelu out hi
__device__ __nv_bfloat16 g_mlo[MTOK*DFF];      // gelu out lo
// packed split weights: u32 word (kp, n) = (bf16(W[2kp+1][n])<<16) | bf16(W[2kp][n])
__device__ uint32_t g_wqkv_hi[NLAYER*(DMODEL/2)*3*DMODEL];
__device__ uint32_t g_wqkv_lo[NLAYER*(DMODEL/2)*3*DMODEL];
__device__ uint32_t g_wproj_hi[NLAYER*(DMODEL/2)*DMODEL];
__device__ uint32_t g_wproj_lo[NLAYER*(DMODEL/2)*DMODEL];
__device__ uint32_t g_w1_hi[NLAYER*(DMODEL/2)*DFF];
__device__ uint32_t g_w1_lo[NLAYER*(DMODEL/2)*DFF];
__device__ uint32_t g_w2_hi[NLAYER*(DFF/2)*DMODEL];
__device__ uint32_t g_w2_lo[NLAYER*(DFF/2)*DMODEL];
__device__ uint32_t g_lmh_hi[(DMODEL/2)*VOCAB];
__device__ uint32_t g_lmh_lo[(DMODEL/2)*VOCAB];
__device__ float g_tce[MTOK];
__device__ float g_tw [MTOK];
__device__ int   g_mflag;                  // 1 = value_mask is uint8, 0 = int32

// ---------------- block reductions (deterministic) ----------------
__device__ __forceinline__ float blockReduceSum(float val) {
    __shared__ float sh[32];
    const int lane = threadIdx.x & 31, wid = threadIdx.x >> 5;
    #pragma unroll
    for (int o = 16; o; o >>= 1) val += __shfl_xor_sync(0xffffffffu, val, o);
    if (lane == 0) sh[wid] = val;
    __syncthreads();
    const int nw = (blockDim.x + 31) >> 5;
    float t = (threadIdx.x < nw) ? sh[threadIdx.x] : 0.0f;
    #pragma unroll
    for (int o = 16; o; o >>= 1) t += __shfl_xor_sync(0xffffffffu, t, o);
    if (threadIdx.x == 0) sh[0] = t;
    __syncthreads();
    t = sh[0];
    __syncthreads();
    return t;
}

__device__ __forceinline__ float blockReduceMax(float val) {
    __shared__ float sh[32];
    const int lane = threadIdx.x & 31, wid = threadIdx.x >> 5;
    #pragma unroll
    for (int o = 16; o; o >>= 1) val = fmaxf(val, __shfl_xor_sync(0xffffffffu, val, o));
    if (lane == 0) sh[wid] = val;
    __syncthreads();
    const int nw = (blockDim.x + 31) >> 5;
    float t = (threadIdx.x < nw) ? sh[threadIdx.x] : -INFINITY;
    #pragma unroll
    for (int o = 16; o; o >>= 1) t = fmaxf(t, __shfl_xor_sync(0xffffffffu, t, o));
    if (threadIdx.x == 0) sh[0] = t;
    __syncthreads();
    t = sh[0];
    __syncthreads();
    return t;
}

// ---------------- hi/lo bf16 split helper ----------------
__device__ __forceinline__ void split_bf16(float a, __nv_bfloat16& hi, __nv_bfloat16& lo) {
    hi = __float2bfloat16(a);
    lo = __float2bfloat16(a - __bfloat162float(hi));
}

// ---------------- cp.async helpers ----------------
__device__ __forceinline__ void cp16(void* sdst, const void* gsrc) {
    uint32_t sa = (uint32_t)__cvta_generic_to_shared(sdst);
    asm volatile("cp.async.cg.shared.global [%0], [%1], 16;" :: "r"(sa), "l"(gsrc));
}
#define CP_COMMIT() asm volatile("cp.async.commit_group;" ::: "memory")
#define CP_WAIT1()  asm volatile("cp.async.wait_group 1;" ::: "memory")

// ---------------- weight split/pack kernels ----------------
__global__ __launch_bounds__(256) void convw_kernel(
    const float* __restrict__ W, uint32_t* __restrict__ Whi, uint32_t* __restrict__ Wlo,
    int K, int N)
{
    const int n  = blockIdx.x * 256 + threadIdx.x;
    const int kp = blockIdx.y;
    const int l  = blockIdx.z;
    const float* Wl = W + (size_t)l * K * N;
    const float a0 = Wl[(size_t)(2 * kp)     * N + n];
    const float a1 = Wl[(size_t)(2 * kp + 1) * N + n];
    __nv_bfloat16 h0, l0, h1, l1;
    split_bf16(a0, h0, l0);
    split_bf16(a1, h1, l1);
    const size_t o = (size_t)l * (K / 2) * N + (size_t)kp * N + n;
    Whi[o] = ((uint32_t)__bfloat16_as_ushort(h1) << 16) | __bfloat16_as_ushort(h0);
    Wlo[o] = ((uint32_t)__bfloat16_as_ushort(l1) << 16) | __bfloat16_as_ushort(l0);
}

__global__ __launch_bounds__(256) void convw_t_kernel(
    const float* __restrict__ W, uint32_t* __restrict__ Whi, uint32_t* __restrict__ Wlo,
    int K, int N)
{
    const int kp = blockIdx.x * 256 + threadIdx.x;
    const int n  = blockIdx.y;
    const float2 a = *(const float2*)(W + (size_t)n * K + 2 * kp);
    __nv_bfloat16 h0, l0, h1, l1;
    split_bf16(a.x, h0, l0);
    split_bf16(a.y, h1, l1);
    const size_t o = (size_t)kp * N + n;
    Whi[o] = ((uint32_t)__bfloat16_as_ushort(h1) << 16) | __bfloat16_as_ushort(h0);
    Wlo[o] = ((uint32_t)__bfloat16_as_ushort(l1) << 16) | __bfloat16_as_ushort(l0);
}

// ---------------- value_mask dtype probe ----------------
__global__ __launch_bounds__(256) void detect_mask_kernel(const unsigned char* __restrict__ m)
{
    __shared__ int sh[32];
    int s = 0;
    for (int i = threadIdx.x; i < 8192; i += 256)
        if (i & 3) s += m[i];
    #pragma unroll
    for (int o = 16; o; o >>= 1) s += __shfl_xor_sync(0xffffffffu, s, o);
    const int lane = threadIdx.x & 31, wid = threadIdx.x >> 5;
    if (lane == 0) sh[wid] = s;
    __syncthreads();
    if (threadIdx.x < 8) {
        int t = sh[threadIdx.x];
        #pragma unroll
        for (int o = 4; o; o >>= 1) t += __shfl_xor_sync(0xffu, t, o);
        if (threadIdx.x == 0) g_mflag = (t != 0) ? 1 : 0;
    }
}

// ---------------- embed ----------------
__global__ __launch_bounds__(256) void embed_kernel(
    const int* __restrict__ ids, const float* __restrict__ tok,
    const float* __restrict__ pos, float* __restrict__ x)
{
    const int m = blockIdx.x;
    const int t = m & (SEQ - 1);
    const int id = ids[m];
    const float4 a = ((const float4*)(tok + (size_t)id * DMODEL))[threadIdx.x];
    const float4 b = ((const float4*)(pos + (size_t)t  * DMODEL))[threadIdx.x];
    ((float4*)(x + (size_t)m * DMODEL))[threadIdx.x] =
        make_float4(a.x + b.x, a.y + b.y, a.z + b.z, a.w + b.w);
}

// ---------------- layernorm -> split bf16 outputs ----------------
__global__ __launch_bounds__(256) void ln_bf16_kernel(
    const float* __restrict__ x, const float* __restrict__ w,
    const float* __restrict__ b, __nv_bfloat16* __restrict__ yhi,
    __nv_bfloat16* __restrict__ ylo)
{
    const int row = blockIdx.x;
    const float4 v = ((const float4*)(x + (size_t)row * DMODEL))[threadIdx.x];
    float s = v.x + v.y + v.z + v.w;
    s = blockReduceSum(s);
    const float mu = s * (1.0f / DMODEL);
    const float d0 = v.x - mu, d1 = v.y - mu, d2 = v.z - mu, d3 = v.w - mu;
    float q = d0*d0 + d1*d1 + d2*d2 + d3*d3;
    q = blockReduceSum(q);
    const float rs = rsqrtf(q * (1.0f / DMODEL) + 1e-5f);
    const float4 w4 = ((const float4*)w)[threadIdx.x];
    const float4 b4 = ((const float4*)b)[threadIdx.x];
    float o0 = d0 * rs * w4.x + b4.x;
    float o1 = d1 * rs * w4.y + b4.y;
    float o2 = d2 * rs * w4.z + b4.z;
    float o3 = d3 * rs * w4.w + b4.w;
    __nv_bfloat16 h0,l0,h1,l1,h2,l2,h3,l3;
    split_bf16(o0,h0,l0); split_bf16(o1,h1,l1); split_bf16(o2,h2,l2); split_bf16(o3,h3,l3);
    const size_t base = (size_t)row * DMODEL + threadIdx.x * 4;
    *(__nv_bfloat162*)(yhi + base)     = __halves2bfloat162(h0, h1);
    *(__nv_bfloat162*)(yhi + base + 2) = __halves2bfloat162(h2, h3);
    *(__nv_bfloat162*)(ylo + base)     = __halves2bfloat162(l0, l1);
    *(__nv_bfloat162*)(ylo + base + 2) = __halves2bfloat162(l2, l3);
}

// ---------------- split-bf16 tensor-core GEMM (cp.async double-buffered) -------
enum { EPI_NONE = 0, EPI_RES = 1, EPI_GELU = 2 };

__device__ __forceinline__ void mma16816(float* d, const uint32_t* a, const uint32_t* b) {
    asm volatile(
        "mma.sync.aligned.m16n8k16.row.col.f32.bf16.bf16.f32 "
        "{%0,%1,%2,%3}, {%4,%5,%6,%7}, {%8,%9}, {%0,%1,%2,%3};"
        : "+f"(d[0]), "+f"(d[1]), "+f"(d[2]), "+f"(d[3])
        : "r"(a[0]), "r"(a[1]), "r"(a[2]), "r"(a[3]), "r"(b[0]), "r"(b[1]));
}

// smem layout constants (u32 units)
#define GSA 20
#define GSB 136
#define A_U32 (128*GSA)                 // 2560
#define B_U32 (16*GSB)                  // 2176
#define STAGE_U32 (2*A_U32 + 2*B_U32)   // 9472
#define GEMM_SMEM_BYTES (2*STAGE_U32*4) // 75776

template<int EPI>
__global__ __launch_bounds__(256) void gemm_bf16s_kernel(
    const __nv_bfloat16* __restrict__ Ahi_, const __nv_bfloat16* __restrict__ Alo_,
    const uint32_t* __restrict__ Bhi, const uint32_t* __restrict__ Blo,
    const float* __restrict__ bias, const float* __restrict__ res,
    float* __restrict__ C, __nv_bfloat16* __restrict__ Chi, __nv_bfloat16* __restrict__ Clo,
    int M, int N, int K)
{
    constexpr int BM = 128, BN = 128, BK = 32;
    extern __shared__ uint32_t dynsmem[];

    const int tid = threadIdx.x;
    const int bm = blockIdx.y * BM;
    const int bn = blockIdx.x * BN;
    const int K2 = K >> 1;
    const uint32_t* A32h = (const uint32_t*)Ahi_;
    const uint32_t* A32l = (const uint32_t*)Alo_;

    const int lane = tid & 31;
    const int g = lane >> 2;
    const int t = lane & 3;
    const int w = tid >> 5;
    const int wm = w >> 2, wn = w & 3;

    // per-thread load coordinates (same pattern both stages)
    const int a_r0 = tid >> 2,        a_c0 = (tid & 3) << 2;          // i=0
    const int a_r1 = (tid + 256) >> 2, a_c1 = ((tid + 256) & 3) << 2;  // i=1
    const int b_k0 = tid >> 5,        b_c0 = (tid & 31) << 2;
    const int b_k1 = (tid + 256) >> 5, b_c1 = ((tid + 256) & 31) << 2;

    float acc[4][4][4];
    #pragma unroll
    for (int mt = 0; mt < 4; mt++)
        #pragma unroll
        for (int nt = 0; nt < 4; nt++)
            #pragma unroll
            for (int i = 0; i < 4; i++) acc[mt][nt][i] = 0.0f;

    const int niter = K / BK;

    // stage issue: copies tile kt into buffer s
    auto issue = [&](int s, int kt) {
        const int kp0 = kt >> 1;
        uint32_t* dAh = dynsmem + s * STAGE_U32;
        uint32_t* dAl = dAh + A_U32;
        uint32_t* dBh = dAl + A_U32;
        uint32_t* dBl = dBh + B_U32;
        {
            const size_t go = (size_t)(bm + a_r0) * K2 + kp0 + a_c0;
            cp16(&dAh[a_r0 * GSA + a_c0], A32h + go);
            cp16(&dAl[a_r0 * GSA + a_c0], A32l + go);
        }
        {
            const size_t go = (size_t)(bm + a_r1) * K2 + kp0 + a_c1;
            cp16(&dAh[a_r1 * GSA + a_c1], A32h + go);
            cp16(&dAl[a_r1 * GSA + a_c1], A32l + go);
        }
        {
            const size_t go = (size_t)(kp0 + b_k0) * N + bn + b_c0;
            cp16(&dBh[b_k0 * GSB + b_c0], Bhi + go);
            cp16(&dBl[b_k0 * GSB + b_c0], Blo + go);
        }
        {
            const size_t go = (size_t)(kp0 + b_k1) * N + bn + b_c1;
            cp16(&dBh[b_k1 * GSB + b_c1], Bhi + go);
            cp16(&dBl[b_k1 * GSB + b_c1], Blo + go);
        }
    };

    issue(0, 0);
    CP_COMMIT();

    for (int it = 0; it < niter; it++) {
        const int s = it & 1;
        if (it + 1 < niter) issue(s ^ 1, (it + 1) * BK);
        CP_COMMIT();
        CP_WAIT1();
        __syncthreads();

        const uint32_t* sAh = dynsmem + s * STAGE_U32;
        const uint32_t* sAl = sAh + A_U32;
        const uint32_t* sBh = sAl + A_U32;
        const uint32_t* sBl = sBh + B_U32;

        #pragma unroll
        for (int ks = 0; ks < 2; ks++) {
            const int kb = ks * 8;
            uint32_t bh[4][2], bl[4][2];
            #pragma unroll
            for (int nt = 0; nt < 4; nt++) {
                const int col = wn * 32 + nt * 8 + g;
                bh[nt][0] = sBh[(kb + t) * GSB + col];
                bh[nt][1] = sBh[(kb + t + 4) * GSB + col];
                bl[nt][0] = sBl[(kb + t) * GSB + col];
                bl[nt][1] = sBl[(kb + t + 4) * GSB + col];
            }
            #pragma unroll
            for (int mt = 0; mt < 4; mt++) {
                const int row = wm * 64 + mt * 16 + g;
                uint32_t ah[4], al[4];
                ah[0] = sAh[(row    ) * GSA + kb + t];
                ah[1] = sAh[(row + 8) * GSA + kb + t];
                ah[2] = sAh[(row    ) * GSA + kb + t + 4];
                ah[3] = sAh[(row + 8) * GSA + kb + t + 4];
                al[0] = sAl[(row    ) * GSA + kb + t];
                al[1] = sAl[(row + 8) * GSA + kb + t];
                al[2] = sAl[(row    ) * GSA + kb + t + 4];
                al[3] = sAl[(row + 8) * GSA + kb + t + 4];
                #pragma unroll
                for (int nt = 0; nt < 4; nt++) mma16816(acc[mt][nt], ah, bh[nt]);
                #pragma unroll
                for (int nt = 0; nt < 4; nt++) mma16816(acc[mt][nt], ah, bl[nt]);
                #pragma unroll
                for (int nt = 0; nt < 4; nt++) mma16816(acc[mt][nt], al, bh[nt]);
            }
        }
        __syncthreads();
    }

    // ---- epilogue ----
    #pragma unroll
    for (int mt = 0; mt < 4; mt++) {
        #pragma unroll
        for (int nt = 0; nt < 4; nt++) {
            const int col = bn + wn * 32 + nt * 8 + 2 * t;
            #pragma unroll
            for (int half = 0; half < 2; half++) {
                const int row = bm + wm * 64 + mt * 16 + g + half * 8;
                float v0 = acc[mt][nt][2 * half + 0];
                float v1 = acc[mt][nt][2 * half + 1];
                if (bias) { v0 += bias[col]; v1 += bias[col + 1]; }
                const size_t o = (size_t)row * N + col;
                if (EPI == EPI_GELU) {
                    v0 = 0.5f * v0 * (1.0f + erff(v0 * 0.70710678118654752f));
                    v1 = 0.5f * v1 * (1.0f + erff(v1 * 0.70710678118654752f));
                    __nv_bfloat16 h0, l0, h1, l1;
                    split_bf16(v0, h0, l0);
                    split_bf16(v1, h1, l1);
                    *(__nv_bfloat162*)(Chi + o) = __halves2bfloat162(h0, h1);
                    *(__nv_bfloat162*)(Clo + o) = __halves2bfloat162(l0, l1);
                } else {
                    if (EPI == EPI_RES) {
                        const float2 r2 = *(const float2*)(res + o);
                        v0 += r2.x; v1 += r2.y;
                    }
                    *(float2*)(C + o) = make_float2(v0, v1);
                }
            }
        }
    }
}

// ---------------- causal flash attention (fp32, 128 queries/block) ----------------
__global__ __launch_bounds__(128) void attn_kernel(
    const float* __restrict__ qkv,
    __nv_bfloat16* __restrict__ ohi, __nv_bfloat16* __restrict__ olo)
{
    const int qt = blockIdx.x, h = blockIdx.y, b = blockIdx.z;
    const int tid = threadIdx.x;                  // 0..127 = query within tile
    const int qg = qt * 128 + tid;
    const size_t mrow = (size_t)b * SEQ + qg;

    __shared__ float Ks[32][64];
    __shared__ float Vs[32][64];
    __shared__ float Sp[32][128];

    float qreg[64];
    {
        const float4* qp = (const float4*)(qkv + mrow * (3 * DMODEL) + h * HEADDIM);
        #pragma unroll
        for (int i = 0; i < 16; i++) {
            const float4 t4 = qp[i];
            qreg[4*i+0] = t4.x; qreg[4*i+1] = t4.y; qreg[4*i+2] = t4.z; qreg[4*i+3] = t4.w;
        }
    }

    float acc[64];
    #pragma unroll
    for (int d = 0; d < 64; d++) acc[d] = 0.0f;
    float m_i = -INFINITY, l_i = 0.0f;
    const float scale = 0.125f;

    const float* kbase = qkv + (size_t)b * SEQ * (3 * DMODEL) + DMODEL     + h * HEADDIM;
    const float* vbase = qkv + (size_t)b * SEQ * (3 * DMODEL) + 2 * DMODEL + h * HEADDIM;

    const int nkt = 4 * qt + 4;                   // 32-row key tiles covering [0,(qt+1)*128)
    for (int kt = 0; kt < nkt; kt++) {
        {
            const int r0 = tid >> 4;              // 0..7
            const int c4 = tid & 15;
            #pragma unroll
            for (int it2 = 0; it2 < 4; it2++) {
                const int r = it2 * 8 + r0;
                const size_t roff = (size_t)(kt * 32 + r) * (3 * DMODEL);
                *(float4*)&Ks[r][c4 * 4] = *(const float4*)(kbase + roff + c4 * 4);
                *(float4*)&Vs[r][c4 * 4] = *(const float4*)(vbase + roff + c4 * 4);
            }
        }
        __syncthreads();

        const int kg0 = kt * 32;
        float tmax = -INFINITY;
        #pragma unroll 2
        for (int j = 0; j < 32; j++) {
            float s = 0.0f;
            const float4* kr = (const float4*)Ks[j];
            #pragma unroll
            for (int i = 0; i < 16; i++) {
                const float4 kf = kr[i];
                s += qreg[4*i+0]*kf.x + qreg[4*i+1]*kf.y + qreg[4*i+2]*kf.z + qreg[4*i+3]*kf.w;
            }
            s *= scale;
            s = (kg0 + j <= qg) ? s : -INFINITY;
            Sp[j][tid] = s;
            tmax = fmaxf(tmax, s);
        }

        const float mnew = fmaxf(m_i, tmax);
        const float corr = expf(m_i - mnew);
        #pragma unroll
        for (int d = 0; d < 64; d++) acc[d] *= corr;

        float lsum = 0.0f;
        #pragma unroll 2
        for (int j = 0; j < 32; j++) {
            const float e = expf(Sp[j][tid] - mnew);
            lsum += e;
            const float4* vr = (const float4*)Vs[j];
            #pragma unroll
            for (int i = 0; i < 16; i++) {
                const float4 vf = vr[i];
                acc[4*i+0] += e * vf.x; acc[4*i+1] += e * vf.y;
                acc[4*i+2] += e * vf.z; acc[4*i+3] += e * vf.w;
            }
        }
        l_i = l_i * corr + lsum;
        m_i = mnew;
        __syncthreads();
    }

    const float inv = 1.0f / l_i;
    const size_t obase = mrow * DMODEL + h * HEADDIM;
    #pragma unroll
    for (int i = 0; i < 16; i++) {
        const float v0 = acc[4*i+0]*inv, v1 = acc[4*i+1]*inv;
        const float v2 = acc[4*i+2]*inv, v3 = acc[4*i+3]*inv;
        __nv_bfloat16 h0,l0,h1,l1,h2,l2,h3,l3;
        split_bf16(v0,h0,l0); split_bf16(v1,h1,l1); split_bf16(v2,h2,l2); split_bf16(v3,h3,l3);
        *(__nv_bfloat162*)(ohi + obase + 4*i)     = __halves2bfloat162(h0, h1);
        *(__nv_bfloat162*)(ohi + obase + 4*i + 2) = __halves2bfloat162(h2, h3);
        *(__nv_bfloat162*)(olo + obase + 4*i)     = __halves2bfloat162(l0, l1);
        *(__nv_bfloat162*)(olo + obase + 4*i + 2) = __halves2bfloat162(l2, l3);
    }
}

// ---------------- loss ----------------
__global__ __launch_bounds__(256) void loss_token_kernel(
    const float* __restrict__ logits, const int* __restrict__ targets,
    const void* __restrict__ vmask,
    float* __restrict__ tce, float* __restrict__ tw)
{
    const int row = blockIdx.x;
    const float* lr = logits + (size_t)row * VOCAB;
    float v[16];
    #pragma unroll
    for (int i = 0; i < 16; i++) v[i] = lr[threadIdx.x + 256 * i];
    float mx = v[0];
    #pragma unroll
    for (int i = 1; i < 16; i++) mx = fmaxf(mx, v[i]);
    mx = blockReduceMax(mx);
    float se = 0.0f;
    #pragma unroll
    for (int i = 0; i < 16; i++) se += expf(v[i] - mx);
    se = blockReduceSum(se);
    if (threadIdx.x == 0) {
        const int tgt = targets[row];
        const float lse = mx + logf(se);
        const float nll = lse - lr[tgt];
        int mv;
        if (g_mflag) mv = ((const unsigned char*)vmask)[row];
        else         mv = ((const int*)vmask)[row];
        const float w = 1.0f + 4.0f * ((mv != 0) ? 1.0f : 0.0f);
        tce[row] = (tgt == 0) ? 0.0f : nll * w;
        tw[row]  = w;
    }
}

__global__ __launch_bounds__(256) void loss_final_kernel(
    const float* __restrict__ tce, const float* __restrict__ tw, float* __restrict__ out)
{
    float a = 0.0f, b = 0.0f;
    for (int i = threadIdx.x; i < MTOK; i += 256) { a += tce[i]; b += tw[i]; }
    a = blockReduceSum(a);
    b = blockReduceSum(b);
    if (threadIdx.x == 0) out[0] = a / b;
}

// ---------------- host driver ----------------
extern "C" void kernel_launch(void* const* d_in, const int* in_sizes, int n_in,
                              void* d_out, int out_size)
{
    (void)in_sizes; (void)n_in;
    const int*   ids   = (const int*)d_in[0];
    const int*   tgts  = (const int*)d_in[1];
    const void*  vmask = (const void*)d_in[2];
    const float* tok   = (const float*)d_in[3];
    const float* pos   = (const float*)d_in[4];
    const float* ln1w  = (const float*)d_in[5];
    const float* ln1b  = (const float*)d_in[6];
    const float* wqkv  = (const float*)d_in[7];
    const float* bqkv  = (const float*)d_in[8];
    const float* wproj = (const float*)d_in[9];
    const float* bproj = (const float*)d_in[10];
    const float* ln2w  = (const float*)d_in[11];
    const float* ln2b  = (const float*)d_in[12];
    const float* w1    = (const float*)d_in[13];
    const float* b1    = (const float*)d_in[14];
    const float* w2    = (const float*)d_in[15];
    const float* b2    = (const float*)d_in[16];
    const float* lnfw  = (const float*)d_in[17];
    const float* lnfb  = (const float*)d_in[18];
    float* out = (float*)d_out;

    float *x, *qkv, *tce, *tw;
    __nv_bfloat16 *hhi, *hlo, *mhi, *mlo;
    uint32_t *wq_hi, *wq_lo, *wp_hi, *wp_lo, *w1_hi, *w1_lo, *w2_hi, *w2_lo, *lm_hi, *lm_lo;
    cudaGetSymbolAddress((void**)&x,    g_x);
    cudaGetSymbolAddress((void**)&qkv,  g_qkv);
    cudaGetSymbolAddress((void**)&hhi,  g_hhi);
    cudaGetSymbolAddress((void**)&hlo,  g_hlo);
    cudaGetSymbolAddress((void**)&mhi,  g_mhi);
    cudaGetSymbolAddress((void**)&mlo,  g_mlo);
    cudaGetSymbolAddress((void**)&wq_hi, g_wqkv_hi);
    cudaGetSymbolAddress((void**)&wq_lo, g_wqkv_lo);
    cudaGetSymbolAddress((void**)&wp_hi, g_wproj_hi);
    cudaGetSymbolAddress((void**)&wp_lo, g_wproj_lo);
    cudaGetSymbolAddress((void**)&w1_hi, g_w1_hi);
    cudaGetSymbolAddress((void**)&w1_lo, g_w1_lo);
    cudaGetSymbolAddress((void**)&w2_hi, g_w2_hi);
    cudaGetSymbolAddress((void**)&w2_lo, g_w2_lo);
    cudaGetSymbolAddress((void**)&lm_hi, g_lmh_hi);
    cudaGetSymbolAddress((void**)&lm_lo, g_lmh_lo);
    cudaGetSymbolAddress((void**)&tce,  g_tce);
    cudaGetSymbolAddress((void**)&tw,   g_tw);

    // allow 75.8KB dynamic smem on the gemm instantiations (attribute set, not alloc)
    cudaFuncSetAttribute(gemm_bf16s_kernel<EPI_NONE>,
                         cudaFuncAttributeMaxDynamicSharedMemorySize, GEMM_SMEM_BYTES);
    cudaFuncSetAttribute(gemm_bf16s_kernel<EPI_RES>,
                         cudaFuncAttributeMaxDynamicSharedMemorySize, GEMM_SMEM_BYTES);
    cudaFuncSetAttribute(gemm_bf16s_kernel<EPI_GELU>,
                         cudaFuncAttributeMaxDynamicSharedMemorySize, GEMM_SMEM_BYTES);

    // ---- split/pack weights ----
    convw_kernel<<<dim3(3*DMODEL/256, DMODEL/2, NLAYER), 256>>>(wqkv,  wq_hi, wq_lo, DMODEL, 3*DMODEL);
    convw_kernel<<<dim3(DMODEL/256,   DMODEL/2, NLAYER), 256>>>(wproj, wp_hi, wp_lo, DMODEL, DMODEL);
    convw_kernel<<<dim3(DFF/256,      DMODEL/2, NLAYER), 256>>>(w1,    w1_hi, w1_lo, DMODEL, DFF);
    convw_kernel<<<dim3(DMODEL/256,   DFF/2,    NLAYER), 256>>>(w2,    w2_hi, w2_lo, DFF,    DMODEL);
    convw_t_kernel<<<dim3((DMODEL/2)/256, VOCAB), 256>>>(tok, lm_hi, lm_lo, DMODEL, VOCAB);

    detect_mask_kernel<<<1, 256>>>((const unsigned char*)vmask);
    embed_kernel<<<MTOK, 256>>>(ids, tok, pos, x);

    const size_t wq_stride = (size_t)(DMODEL/2) * 3 * DMODEL;
    const size_t wp_stride = (size_t)(DMODEL/2) * DMODEL;
    const size_t w1_stride = (size_t)(DMODEL/2) * DFF;
    const size_t w2_stride = (size_t)(DFF/2)    * DMODEL;

    for (int l = 0; l < NLAYER; l++) {
        ln_bf16_kernel<<<MTOK, 256>>>(x, ln1w + l*DMODEL, ln1b + l*DMODEL, hhi, hlo);

        gemm_bf16s_kernel<EPI_NONE><<<dim3(3*DMODEL/128, MTOK/128), 256, GEMM_SMEM_BYTES>>>(
            hhi, hlo, wq_hi + l*wq_stride, wq_lo + l*wq_stride,
            bqkv + (size_t)l*3*DMODEL, nullptr, qkv, nullptr, nullptr,
            MTOK, 3*DMODEL, DMODEL);

        attn_kernel<<<dim3(SEQ/128, NHEAD, BATCH), 128>>>(qkv, hhi, hlo);

        gemm_bf16s_kernel<EPI_RES><<<dim3(DMODEL/128, MTOK/128), 256, GEMM_SMEM_BYTES>>>(
            hhi, hlo, wp_hi + l*wp_stride, wp_lo + l*wp_stride,
            bproj + (size_t)l*DMODEL, x, x, nullptr, nullptr,
            MTOK, DMODEL, DMODEL);

        ln_bf16_kernel<<<MTOK, 256>>>(x, ln2w + l*DMODEL, ln2b + l*DMODEL, hhi, hlo);

        gemm_bf16s_kernel<EPI_GELU><<<dim3(DFF/128, MTOK/128), 256, GEMM_SMEM_BYTES>>>(
            hhi, hlo, w1_hi + l*w1_stride, w1_lo + l*w1_stride,
            b1 + (size_t)l*DFF, nullptr, nullptr, mhi, mlo,
            MTOK, DFF, DMODEL);

        gemm_bf16s_kernel<EPI_RES><<<dim3(DMODEL/128, MTOK/128), 256, GEMM_SMEM_BYTES>>>(
            mhi, mlo, w2_hi + l*w2_stride, w2_lo + l*w2_stride,
            b2 + (size_t)l*DMODEL, x, x, nullptr, nullptr,
            MTOK, DMODEL, DFF);
    }

    ln_bf16_kernel<<<MTOK, 256>>>(x, lnfw, lnfb, hhi, hlo);

    gemm_bf16s_kernel<EPI_NONE><<<dim3(VOCAB/128, MTOK/128), 256, GEMM_SMEM_BYTES>>>(
        hhi, hlo, lm_hi, lm_lo, nullptr, nullptr, out, nullptr, nullptr,
        MTOK, VOCAB, DMODEL);

    if (out_size > MTOK * VOCAB) {
        loss_token_kernel<<<MTOK, 256>>>(out, tgts, vmask, tce, tw);
        loss_final_kernel<<<1, 256>>>(tce, tw, out + (size_t)MTOK * VOCAB);
    }
}

// round 9
// speedup vs baseline: 2.0949x; 1.1158x over previous
#include <cuda_runtime.h>
#include <cuda_bf16.h>
#include <math.h>
#include <stdint.h>

// ---------------- problem constants ----------------
#define NLAYER   8
#define DMODEL   1024
#define NHEAD    16
#define HEADDIM  64
#define DFF      4096
#define VOCAB    4096
#define BATCH    4
#define SEQ      2048
#define MTOK     (BATCH*SEQ)      // 8192 tokens

// ---------------- scratch (device globals; no allocation allowed) ----------------
__device__ float g_x  [MTOK*DMODEL];       // residual stream (fp32)
__device__ float g_qkv[MTOK*3*DMODEL];     // qkv (fp32, attention input)
__device__ __nv_bfloat16 g_hhi[MTOK*DMODEL];
__device__ __nv_bfloat16 g_hlo[MTOK*DMODEL];
__device__ __nv_bfloat16 g_mhi[MTOK*DFF];
__device__ __nv_bfloat16 g_mlo[MTOK*DFF];
// split weights, N-major [L][N][K] bf16 (B^T layout; TN gemm via ldmatrix)
__device__ __nv_bfloat16 g_wqkv_hi[NLAYER*3*DMODEL*DMODEL];
__device__ __nv_bfloat16 g_wqkv_lo[NLAYER*3*DMODEL*DMODEL];
__device__ __nv_bfloat16 g_wproj_hi[NLAYER*DMODEL*DMODEL];
__device__ __nv_bfloat16 g_wproj_lo[NLAYER*DMODEL*DMODEL];
__device__ __nv_bfloat16 g_w1_hi[NLAYER*DFF*DMODEL];
__device__ __nv_bfloat16 g_w1_lo[NLAYER*DFF*DMODEL];
__device__ __nv_bfloat16 g_w2_hi[NLAYER*DMODEL*DFF];
__device__ __nv_bfloat16 g_w2_lo[NLAYER*DMODEL*DFF];
__device__ __nv_bfloat16 g_lmh_hi[VOCAB*DMODEL];
__device__ __nv_bfloat16 g_lmh_lo[VOCAB*DMODEL];
__device__ float g_tce[MTOK];
__device__ float g_tw [MTOK];
__device__ int   g_mflag;

// ---------------- block reductions ----------------
__device__ __forceinline__ float blockReduceSum(float val) {
    __shared__ float sh[32];
    const int lane = threadIdx.x & 31, wid = threadIdx.x >> 5;
    #pragma unroll
    for (int o = 16; o; o >>= 1) val += __shfl_xor_sync(0xffffffffu, val, o);
    if (lane == 0) sh[wid] = val;
    __syncthreads();
    const int nw = (blockDim.x + 31) >> 5;
    float t = (threadIdx.x < nw) ? sh[threadIdx.x] : 0.0f;
    #pragma unroll
    for (int o = 16; o; o >>= 1) t += __shfl_xor_sync(0xffffffffu, t, o);
    if (threadIdx.x == 0) sh[0] = t;
    __syncthreads();
    t = sh[0];
    __syncthreads();
    return t;
}

__device__ __forceinline__ float blockReduceMax(float val) {
    __shared__ float sh[32];
    const int lane = threadIdx.x & 31, wid = threadIdx.x >> 5;
    #pragma unroll
    for (int o = 16; o; o >>= 1) val = fmaxf(val, __shfl_xor_sync(0xffffffffu, val, o));
    if (lane == 0) sh[wid] = val;
    __syncthreads();
    const int nw = (blockDim.x + 31) >> 5;
    float t = (threadIdx.x < nw) ? sh[threadIdx.x] : -INFINITY;
    #pragma unroll
    for (int o = 16; o; o >>= 1) t = fmaxf(t, __shfl_xor_sync(0xffffffffu, t, o));
    if (threadIdx.x == 0) sh[0] = t;
    __syncthreads();
    t = sh[0];
    __syncthreads();
    return t;
}

// ---------------- helpers ----------------
__device__ __forceinline__ void split_bf16(float a, __nv_bfloat16& hi, __nv_bfloat16& lo) {
    hi = __float2bfloat16(a);
    lo = __float2bfloat16(a - __bfloat162float(hi));
}

__device__ __forceinline__ void cp16(void* sdst, const void* gsrc) {
    uint32_t sa = (uint32_t)__cvta_generic_to_shared(sdst);
    asm volatile("cp.async.cg.shared.global [%0], [%1], 16;" :: "r"(sa), "l"(gsrc));
}
#define CP_COMMIT() asm volatile("cp.async.commit_group;" ::: "memory")

__device__ __forceinline__ uint32_t smem_u32(const void* p) {
    return (uint32_t)__cvta_generic_to_shared(p);
}

#define SWZ128(off) ((off) ^ (((off) >> 3) & 0x70))

__device__ __forceinline__ void mma16816(float* d, const uint32_t* a, const uint32_t* b) {
    asm volatile(
        "mma.sync.aligned.m16n8k16.row.col.f32.bf16.bf16.f32 "
        "{%0,%1,%2,%3}, {%4,%5,%6,%7}, {%8,%9}, {%0,%1,%2,%3};"
        : "+f"(d[0]), "+f"(d[1]), "+f"(d[2]), "+f"(d[3])
        : "r"(a[0]), "r"(a[1]), "r"(a[2]), "r"(a[3]), "r"(b[0]), "r"(b[1]));
}

__device__ __forceinline__ void ldsm4(uint32_t* r, uint32_t addr) {
    asm volatile("ldmatrix.sync.aligned.m8n8.x4.shared.b16 {%0,%1,%2,%3}, [%4];"
                 : "=r"(r[0]), "=r"(r[1]), "=r"(r[2]), "=r"(r[3]) : "r"(addr));
}

// ---------------- weight pack kernels ----------------
// W [K][N] fp32 -> Whi/Wlo bf16 [N][K] (tiled transpose + split)
__global__ __launch_bounds__(256) void convw_nt(
    const float* __restrict__ W, __nv_bfloat16* __restrict__ Whi,
    __nv_bfloat16* __restrict__ Wlo, int K, int N)
{
    __shared__ float tile[32][33];
    const int tx = threadIdx.x & 31, ty = threadIdx.x >> 5;
    const int n0 = blockIdx.x * 32, k0 = blockIdx.y * 32;
    const int l = blockIdx.z;
    const float* Wl = W + (size_t)l * K * N;
    #pragma unroll
    for (int i = ty; i < 32; i += 8)
        tile[i][tx] = Wl[(size_t)(k0 + i) * N + n0 + tx];
    __syncthreads();
    __nv_bfloat16* Hl = Whi + (size_t)l * N * K;
    __nv_bfloat16* Ll = Wlo + (size_t)l * N * K;
    #pragma unroll
    for (int i = ty; i < 32; i += 8) {
        __nv_bfloat16 h, lo;
        split_bf16(tile[tx][i], h, lo);   // = W[k0+tx][n0+i]
        Hl[(size_t)(n0 + i) * K + k0 + tx] = h;
        Ll[(size_t)(n0 + i) * K + k0 + tx] = lo;
    }
}

// elementwise split (lm_head: tok already [V][K])
__global__ __launch_bounds__(256) void convsplit(
    const float* __restrict__ W, __nv_bfloat16* __restrict__ hi, __nv_bfloat16* __restrict__ lo)
{
    const int i = blockIdx.x * 256 + threadIdx.x;
    __nv_bfloat16 h, l;
    split_bf16(W[i], h, l);
    hi[i] = h; lo[i] = l;
}

// ---------------- value_mask dtype probe ----------------
__global__ __launch_bounds__(256) void detect_mask_kernel(const unsigned char* __restrict__ m)
{
    __shared__ int sh[32];
    int s = 0;
    for (int i = threadIdx.x; i < 8192; i += 256)
        if (i & 3) s += m[i];
    #pragma unroll
    for (int o = 16; o; o >>= 1) s += __shfl_xor_sync(0xffffffffu, s, o);
    const int lane = threadIdx.x & 31, wid = threadIdx.x >> 5;
    if (lane == 0) sh[wid] = s;
    __syncthreads();
    if (threadIdx.x < 8) {
        int t = sh[threadIdx.x];
        #pragma unroll
        for (int o = 4; o; o >>= 1) t += __shfl_xor_sync(0xffu, t, o);
        if (threadIdx.x == 0) g_mflag = (t != 0) ? 1 : 0;
    }
}

// ---------------- embed ----------------
__global__ __launch_bounds__(256) void embed_kernel(
    const int* __restrict__ ids, const float* __restrict__ tok,
    const float* __restrict__ pos, float* __restrict__ x)
{
    const int m = blockIdx.x;
    const int t = m & (SEQ - 1);
    const int id = ids[m];
    const float4 a = ((const float4*)(tok + (size_t)id * DMODEL))[threadIdx.x];
    const float4 b = ((const float4*)(pos + (size_t)t  * DMODEL))[threadIdx.x];
    ((float4*)(x + (size_t)m * DMODEL))[threadIdx.x] =
        make_float4(a.x + b.x, a.y + b.y, a.z + b.z, a.w + b.w);
}

// ---------------- layernorm -> split bf16 ----------------
__global__ __launch_bounds__(256) void ln_bf16_kernel(
    const float* __restrict__ x, const float* __restrict__ w,
    const float* __restrict__ b, __nv_bfloat16* __restrict__ yhi,
    __nv_bfloat16* __restrict__ ylo)
{
    const int row = blockIdx.x;
    const float4 v = ((const float4*)(x + (size_t)row * DMODEL))[threadIdx.x];
    float s = v.x + v.y + v.z + v.w;
    s = blockReduceSum(s);
    const float mu = s * (1.0f / DMODEL);
    const float d0 = v.x - mu, d1 = v.y - mu, d2 = v.z - mu, d3 = v.w - mu;
    float q = d0*d0 + d1*d1 + d2*d2 + d3*d3;
    q = blockReduceSum(q);
    const float rs = rsqrtf(q * (1.0f / DMODEL) + 1e-5f);
    const float4 w4 = ((const float4*)w)[threadIdx.x];
    const float4 b4 = ((const float4*)b)[threadIdx.x];
    float o0 = d0 * rs * w4.x + b4.x;
    float o1 = d1 * rs * w4.y + b4.y;
    float o2 = d2 * rs * w4.z + b4.z;
    float o3 = d3 * rs * w4.w + b4.w;
    __nv_bfloat16 h0,l0,h1,l1,h2,l2,h3,l3;
    split_bf16(o0,h0,l0); split_bf16(o1,h1,l1); split_bf16(o2,h2,l2); split_bf16(o3,h3,l3);
    const size_t base = (size_t)row * DMODEL + threadIdx.x * 4;
    *(__nv_bfloat162*)(yhi + base)     = __halves2bfloat162(h0, h1);
    *(__nv_bfloat162*)(yhi + base + 2) = __halves2bfloat162(h2, h3);
    *(__nv_bfloat162*)(ylo + base)     = __halves2bfloat162(l0, l1);
    *(__nv_bfloat162*)(ylo + base + 2) = __halves2bfloat162(l2, l3);
}

// ---------------- split-bf16 mma GEMM with ldmatrix + cp.async -----------------
// C[M,N] = (Ahi+Alo)[M][K] @ (Bhi+Blo)[N][K]^T, fp32 accum, 3 products.
// CTA 128x128, BK=64. smem: 2 stages x {Ah,Al,Bh,Bl} each 128rows x 128B SW128.
enum { EPI_NONE = 0, EPI_RES = 1, EPI_GELU = 2 };

#define STAGE_BYTES 65536
#define GEMM_SMEM_BYTES (2*STAGE_BYTES)   // 131072

template<int EPI>
__global__ __launch_bounds__(256, 1) void gemm_ldsm_kernel(
    const __nv_bfloat16* __restrict__ Ahi, const __nv_bfloat16* __restrict__ Alo,
    const __nv_bfloat16* __restrict__ Bhi, const __nv_bfloat16* __restrict__ Blo,
    const float* __restrict__ bias, const float* __restrict__ res,
    float* __restrict__ C, __nv_bfloat16* __restrict__ Chi, __nv_bfloat16* __restrict__ Clo,
    int M, int N, int K)
{
    extern __shared__ __align__(1024) char smem[];
    const uint32_t sb = smem_u32(smem);
    const int tid = threadIdx.x, lane = tid & 31, wid = tid >> 5;
    const int wm = wid >> 2, wn = wid & 3;              // warp tile (wm*64, wn*32)
    const int bm = blockIdx.y * 128, bn = blockIdx.x * 128;

    float acc[4][4][4];
    #pragma unroll
    for (int mt = 0; mt < 4; mt++)
        #pragma unroll
        for (int nt = 0; nt < 4; nt++)
            #pragma unroll
            for (int i = 0; i < 4; i++) acc[mt][nt][i] = 0.0f;

    // fill stage s with k-atom kt (64 k elems): 4 tiles of 128 rows x 128B
    auto fill = [&](int s, int kt) {
        char* st = smem + s * STAGE_BYTES;
        const int k0 = kt << 6;
        #pragma unroll
        for (int i = 0; i < 4; i++) {
            const int idx = tid + i * 256;              // 0..1023
            const int row = idx >> 3, c16 = idx & 7;
            const uint32_t sw = SWZ128((uint32_t)((row << 7) + (c16 << 4)));
            const size_t ga = (size_t)(bm + row) * K + k0 + c16 * 8;
            const size_t gb = (size_t)(bn + row) * K + k0 + c16 * 8;
            cp16(st + sw,         Ahi + ga);
            cp16(st + 16384 + sw, Alo + ga);
            cp16(st + 32768 + sw, Bhi + gb);
            cp16(st + 49152 + sw, Blo + gb);
        }
    };

    // per-lane ldmatrix address components
    const int laneRA = lane & 15;                       // A: row within m16
    const int laneCA = (lane >> 4) << 4;                // A: +16B for k-hi half
    const int laneRB = (lane & 7) + ((lane >> 4) << 3); // B: row within n16
    const int laneCB = ((lane >> 3) & 1) << 4;          // B: +16B for k-hi half

    const int niter = K >> 6;
    fill(0, 0); CP_COMMIT();

    for (int it = 0; it < niter; it++) {
        const int s = it & 1;
        if (it + 1 < niter) {
            fill(s ^ 1, it + 1); CP_COMMIT();
            asm volatile("cp.async.wait_group 1;" ::: "memory");
        } else {
            asm volatile("cp.async.wait_group 0;" ::: "memory");
        }
        __syncthreads();

        const uint32_t aH = sb + s * STAGE_BYTES;
        const uint32_t aL = aH + 16384;
        const uint32_t bH = aH + 32768;
        const uint32_t bL = aH + 49152;

        #pragma unroll
        for (int k16 = 0; k16 < 4; k16++) {
            const int kb = k16 * 32;                    // byte offset of this k16
            uint32_t ah[4][4], al[4][4], bh[4][2], bl[4][2];
            #pragma unroll
            for (int mt = 0; mt < 4; mt++) {
                const uint32_t off = SWZ128(
                    (uint32_t)(((wm * 64 + mt * 16 + laneRA) << 7) + kb + laneCA));
                ldsm4(ah[mt], aH + off);
                ldsm4(al[mt], aL + off);
            }
            #pragma unroll
            for (int j = 0; j < 2; j++) {               // two n16 groups -> 4 n8 tiles
                const uint32_t off = SWZ128(
                    (uint32_t)(((wn * 32 + j * 16 + laneRB) << 7) + kb + laneCB));
                ldsm4(&bh[j * 2][0], bH + off);
                ldsm4(&bl[j * 2][0], bL + off);
            }
            // product-major: RAW distance on each acc = 16 HMMAs
            #pragma unroll
            for (int mt = 0; mt < 4; mt++)
                #pragma unroll
                for (int nt = 0; nt < 4; nt++) mma16816(acc[mt][nt], ah[mt], bh[nt]);
            #pragma unroll
            for (int mt = 0; mt < 4; mt++)
                #pragma unroll
                for (int nt = 0; nt < 4; nt++) mma16816(acc[mt][nt], ah[mt], bl[nt]);
            #pragma unroll
            for (int mt = 0; mt < 4; mt++)
                #pragma unroll
                for (int nt = 0; nt < 4; nt++) mma16816(acc[mt][nt], al[mt], bh[nt]);
        }
        __syncthreads();
    }

    // ---- epilogue (same mapping as proven R6 kernel) ----
    const int g = lane >> 2, t = lane & 3;
    #pragma unroll
    for (int mt = 0; mt < 4; mt++) {
        #pragma unroll
        for (int nt = 0; nt < 4; nt++) {
            const int col = bn + wn * 32 + nt * 8 + 2 * t;
            #pragma unroll
            for (int half = 0; half < 2; half++) {
                const int row = bm + wm * 64 + mt * 16 + g + half * 8;
                float v0 = acc[mt][nt][2 * half + 0];
                float v1 = acc[mt][nt][2 * half + 1];
                if (bias) { v0 += bias[col]; v1 += bias[col + 1]; }
                const size_t o = (size_t)row * N + col;
                if (EPI == EPI_GELU) {
                    v0 = 0.5f * v0 * (1.0f + erff(v0 * 0.70710678118654752f));
                    v1 = 0.5f * v1 * (1.0f + erff(v1 * 0.70710678118654752f));
                    __nv_bfloat16 h0, l0, h1, l1;
                    split_bf16(v0, h0, l0);
                    split_bf16(v1, h1, l1);
                    *(__nv_bfloat162*)(Chi + o) = __halves2bfloat162(h0, h1);
                    *(__nv_bfloat162*)(Clo + o) = __halves2bfloat162(l0, l1);
                } else {
                    if (EPI == EPI_RES) {
                        const float2 r2 = *(const float2*)(res + o);
                        v0 += r2.x; v1 += r2.y;
                    }
                    *(float2*)(C + o) = make_float2(v0, v1);
                }
            }
        }
    }
}

// ---------------- causal flash attention (fp32, 128 queries/block) ----------------
__global__ __launch_bounds__(128) void attn_kernel(
    const float* __restrict__ qkv,
    __nv_bfloat16* __restrict__ ohi, __nv_bfloat16* __restrict__ olo)
{
    const int qt = blockIdx.x, h = blockIdx.y, b = blockIdx.z;
    const int tid = threadIdx.x;
    const int qg = qt * 128 + tid;
    const size_t mrow = (size_t)b * SEQ + qg;

    __shared__ float Ks[32][64];
    __shared__ float Vs[32][64];
    __shared__ float Sp[32][128];

    float qreg[64];
    {
        const float4* qp = (const float4*)(qkv + mrow * (3 * DMODEL) + h * HEADDIM);
        #pragma unroll
        for (int i = 0; i < 16; i++) {
            const float4 t4 = qp[i];
            qreg[4*i+0] = t4.x; qreg[4*i+1] = t4.y; qreg[4*i+2] = t4.z; qreg[4*i+3] = t4.w;
        }
    }

    float acc[64];
    #pragma unroll
    for (int d = 0; d < 64; d++) acc[d] = 0.0f;
    float m_i = -INFINITY, l_i = 0.0f;
    const float scale = 0.125f;

    const float* kbase = qkv + (size_t)b * SEQ * (3 * DMODEL) + DMODEL     + h * HEADDIM;
    const float* vbase = qkv + (size_t)b * SEQ * (3 * DMODEL) + 2 * DMODEL + h * HEADDIM;

    const int nkt = 4 * qt + 4;
    for (int kt = 0; kt < nkt; kt++) {
        {
            const int r0 = tid >> 4;
            const int c4 = tid & 15;
            #pragma unroll
            for (int it2 = 0; it2 < 4; it2++) {
                const int r = it2 * 8 + r0;
                const size_t roff = (size_t)(kt * 32 + r) * (3 * DMODEL);
                *(float4*)&Ks[r][c4 * 4] = *(const float4*)(kbase + roff + c4 * 4);
                *(float4*)&Vs[r][c4 * 4] = *(const float4*)(vbase + roff + c4 * 4);
            }
        }
        __syncthreads();

        const int kg0 = kt * 32;
        float tmax = -INFINITY;
        #pragma unroll 2
        for (int j = 0; j < 32; j++) {
            float s = 0.0f;
            const float4* kr = (const float4*)Ks[j];
            #pragma unroll
            for (int i = 0; i < 16; i++) {
                const float4 kf = kr[i];
                s += qreg[4*i+0]*kf.x + qreg[4*i+1]*kf.y + qreg[4*i+2]*kf.z + qreg[4*i+3]*kf.w;
            }
            s *= scale;
            s = (kg0 + j <= qg) ? s : -INFINITY;
            Sp[j][tid] = s;
            tmax = fmaxf(tmax, s);
        }

        const float mnew = fmaxf(m_i, tmax);
        const float corr = expf(m_i - mnew);
        #pragma unroll
        for (int d = 0; d < 64; d++) acc[d] *= corr;

        float lsum = 0.0f;
        #pragma unroll 2
        for (int j = 0; j < 32; j++) {
            const float e = expf(Sp[j][tid] - mnew);
            lsum += e;
            const float4* vr = (const float4*)Vs[j];
            #pragma unroll
            for (int i = 0; i < 16; i++) {
                const float4 vf = vr[i];
                acc[4*i+0] += e * vf.x; acc[4*i+1] += e * vf.y;
                acc[4*i+2] += e * vf.z; acc[4*i+3] += e * vf.w;
            }
        }
        l_i = l_i * corr + lsum;
        m_i = mnew;
        __syncthreads();
    }

    const float inv = 1.0f / l_i;
    const size_t obase = mrow * DMODEL + h * HEADDIM;
    #pragma unroll
    for (int i = 0; i < 16; i++) {
        const float v0 = acc[4*i+0]*inv, v1 = acc[4*i+1]*inv;
        const float v2 = acc[4*i+2]*inv, v3 = acc[4*i+3]*inv;
        __nv_bfloat16 h0,l0,h1,l1,h2,l2,h3,l3;
        split_bf16(v0,h0,l0); split_bf16(v1,h1,l1); split_bf16(v2,h2,l2); split_bf16(v3,h3,l3);
        *(__nv_bfloat162*)(ohi + obase + 4*i)     = __halves2bfloat162(h0, h1);
        *(__nv_bfloat162*)(ohi + obase + 4*i + 2) = __halves2bfloat162(h2, h3);
        *(__nv_bfloat162*)(olo + obase + 4*i)     = __halves2bfloat162(l0, l1);
        *(__nv_bfloat162*)(olo + obase + 4*i + 2) = __halves2bfloat162(l2, l3);
    }
}

// ---------------- loss ----------------
__global__ __launch_bounds__(256) void loss_token_kernel(
    const float* __restrict__ logits, const int* __restrict__ targets,
    const void* __restrict__ vmask,
    float* __restrict__ tce, float* __restrict__ tw)
{
    const int row = blockIdx.x;
    const float* lr = logits + (size_t)row * VOCAB;
    float v[16];
    #pragma unroll
    for (int i = 0; i < 16; i++) v[i] = lr[threadIdx.x + 256 * i];
    float mx = v[0];
    #pragma unroll
    for (int i = 1; i < 16; i++) mx = fmaxf(mx, v[i]);
    mx = blockReduceMax(mx);
    float se = 0.0f;
    #pragma unroll
    for (int i = 0; i < 16; i++) se += expf(v[i] - mx);
    se = blockReduceSum(se);
    if (threadIdx.x == 0) {
        const int tgt = targets[row];
        const float lse = mx + logf(se);
        const float nll = lse - lr[tgt];
        int mv;
        if (g_mflag) mv = ((const unsigned char*)vmask)[row];
        else         mv = ((const int*)vmask)[row];
        const float w = 1.0f + 4.0f * ((mv != 0) ? 1.0f : 0.0f);
        tce[row] = (tgt == 0) ? 0.0f : nll * w;
        tw[row]  = w;
    }
}

__global__ __launch_bounds__(256) void loss_final_kernel(
    const float* __restrict__ tce, const float* __restrict__ tw, float* __restrict__ out)
{
    float a = 0.0f, b = 0.0f;
    for (int i = threadIdx.x; i < MTOK; i += 256) { a += tce[i]; b += tw[i]; }
    a = blockReduceSum(a);
    b = blockReduceSum(b);
    if (threadIdx.x == 0) out[0] = a / b;
}

// ---------------- host driver ----------------
extern "C" void kernel_launch(void* const* d_in, const int* in_sizes, int n_in,
                              void* d_out, int out_size)
{
    (void)in_sizes; (void)n_in;
    const int*   ids   = (const int*)d_in[0];
    const int*   tgts  = (const int*)d_in[1];
    const void*  vmask = (const void*)d_in[2];
    const float* tok   = (const float*)d_in[3];
    const float* pos   = (const float*)d_in[4];
    const float* ln1w  = (const float*)d_in[5];
    const float* ln1b  = (const float*)d_in[6];
    const float* wqkv  = (const float*)d_in[7];
    const float* bqkv  = (const float*)d_in[8];
    const float* wproj = (const float*)d_in[9];
    const float* bproj = (const float*)d_in[10];
    const float* ln2w  = (const float*)d_in[11];
    const float* ln2b  = (const float*)d_in[12];
    const float* w1    = (const float*)d_in[13];
    const float* b1    = (const float*)d_in[14];
    const float* w2    = (const float*)d_in[15];
    const float* b2    = (const float*)d_in[16];
    const float* lnfw  = (const float*)d_in[17];
    const float* lnfb  = (const float*)d_in[18];
    float* out = (float*)d_out;

    float *x, *qkv, *tce, *tw;
    __nv_bfloat16 *hhi, *hlo, *mhi, *mlo;
    __nv_bfloat16 *wq_hi, *wq_lo, *wp_hi, *wp_lo, *w1_hi, *w1_lo, *w2_hi, *w2_lo, *lm_hi, *lm_lo;
    cudaGetSymbolAddress((void**)&x,    g_x);
    cudaGetSymbolAddress((void**)&qkv,  g_qkv);
    cudaGetSymbolAddress((void**)&hhi,  g_hhi);
    cudaGetSymbolAddress((void**)&hlo,  g_hlo);
    cudaGetSymbolAddress((void**)&mhi,  g_mhi);
    cudaGetSymbolAddress((void**)&mlo,  g_mlo);
    cudaGetSymbolAddress((void**)&wq_hi, g_wqkv_hi);
    cudaGetSymbolAddress((void**)&wq_lo, g_wqkv_lo);
    cudaGetSymbolAddress((void**)&wp_hi, g_wproj_hi);
    cudaGetSymbolAddress((void**)&wp_lo, g_wproj_lo);
    cudaGetSymbolAddress((void**)&w1_hi, g_w1_hi);
    cudaGetSymbolAddress((void**)&w1_lo, g_w1_lo);
    cudaGetSymbolAddress((void**)&w2_hi, g_w2_hi);
    cudaGetSymbolAddress((void**)&w2_lo, g_w2_lo);
    cudaGetSymbolAddress((void**)&lm_hi, g_lmh_hi);
    cudaGetSymbolAddress((void**)&lm_lo, g_lmh_lo);
    cudaGetSymbolAddress((void**)&tce,  g_tce);
    cudaGetSymbolAddress((void**)&tw,   g_tw);

    cudaFuncSetAttribute(gemm_ldsm_kernel<EPI_NONE>,
                         cudaFuncAttributeMaxDynamicSharedMemorySize, GEMM_SMEM_BYTES);
    cudaFuncSetAttribute(gemm_ldsm_kernel<EPI_RES>,
                         cudaFuncAttributeMaxDynamicSharedMemorySize, GEMM_SMEM_BYTES);
    cudaFuncSetAttribute(gemm_ldsm_kernel<EPI_GELU>,
                         cudaFuncAttributeMaxDynamicSharedMemorySize, GEMM_SMEM_BYTES);

    // ---- pack weights: [K][N] fp32 -> [N][K] bf16 hi/lo ----
    convw_nt<<<dim3(3*DMODEL/32, DMODEL/32, NLAYER), 256>>>(wqkv,  wq_hi, wq_lo, DMODEL, 3*DMODEL);
    convw_nt<<<dim3(DMODEL/32,   DMODEL/32, NLAYER), 256>>>(wproj, wp_hi, wp_lo, DMODEL, DMODEL);
    convw_nt<<<dim3(DFF/32,      DMODEL/32, NLAYER), 256>>>(w1,    w1_hi, w1_lo, DMODEL, DFF);
    convw_nt<<<dim3(DMODEL/32,   DFF/32,    NLAYER), 256>>>(w2,    w2_hi, w2_lo, DFF,    DMODEL);
    convsplit<<<VOCAB*DMODEL/256, 256>>>(tok, lm_hi, lm_lo);

    detect_mask_kernel<<<1, 256>>>((const unsigned char*)vmask);
    embed_kernel<<<MTOK, 256>>>(ids, tok, pos, x);

    const size_t wq_s = (size_t)3*DMODEL*DMODEL;
    const size_t wp_s = (size_t)DMODEL*DMODEL;
    const size_t w1_s = (size_t)DFF*DMODEL;
    const size_t w2_s = (size_t)DMODEL*DFF;

    for (int l = 0; l < NLAYER; l++) {
        ln_bf16_kernel<<<MTOK, 256>>>(x, ln1w + l*DMODEL, ln1b + l*DMODEL, hhi, hlo);

        gemm_ldsm_kernel<EPI_NONE><<<dim3(3*DMODEL/128, MTOK/128), 256, GEMM_SMEM_BYTES>>>(
            hhi, hlo, wq_hi + l*wq_s, wq_lo + l*wq_s,
            bqkv + (size_t)l*3*DMODEL, nullptr, qkv, nullptr, nullptr,
            MTOK, 3*DMODEL, DMODEL);

        attn_kernel<<<dim3(SEQ/128, NHEAD, BATCH), 128>>>(qkv, hhi, hlo);

        gemm_ldsm_kernel<EPI_RES><<<dim3(DMODEL/128, MTOK/128), 256, GEMM_SMEM_BYTES>>>(
            hhi, hlo, wp_hi + l*wp_s, wp_lo + l*wp_s,
            bproj + (size_t)l*DMODEL, x, x, nullptr, nullptr,
            MTOK, DMODEL, DMODEL);

        ln_bf16_kernel<<<MTOK, 256>>>(x, ln2w + l*DMODEL, ln2b + l*DMODEL, hhi, hlo);

        gemm_ldsm_kernel<EPI_GELU><<<dim3(DFF/128, MTOK/128), 256, GEMM_SMEM_BYTES>>>(
            hhi, hlo, w1_hi + l*w1_s, w1_lo + l*w1_s,
            b1 + (size_t)l*DFF, nullptr, nullptr, mhi, mlo,
            MTOK, DFF, DMODEL);

        gemm_ldsm_kernel<EPI_RES><<<dim3(DMODEL/128, MTOK/128), 256, GEMM_SMEM_BYTES>>>(
            mhi, mlo, w2_hi + l*w2_s, w2_lo + l*w2_s,
            b2 + (size_t)l*DMODEL, x, x, nullptr, nullptr,
            MTOK, DMODEL, DFF);
    }

    ln_bf16_kernel<<<MTOK, 256>>>(x, lnfw, lnfb, hhi, hlo);

    gemm_ldsm_kernel<EPI_NONE><<<dim3(VOCAB/128, MTOK/128), 256, GEMM_SMEM_BYTES>>>(
        hhi, hlo, lm_hi, lm_lo, nullptr, nullptr, out, nullptr, nullptr,
        MTOK, VOCAB, DMODEL);

    if (out_size > MTOK * VOCAB) {
        loss_token_kernel<<<MTOK, 256>>>(out, tgts, vmask, tce, tw);
        loss_final_kernel<<<1, 256>>>(tce, tw, out + (size_t)MTOK * VOCAB);
    }
}